// round 3
// baseline (speedup 1.0000x reference)
#include <cuda_runtime.h>
#include <cuda_bf16.h>
#include <mma.h>
#include <math.h>
#include <cstdint>
#include <cstddef>

using namespace nvcuda;

#define DMODEL 1024
#define DFF    4096
#define NHEADS 16
#define HEADD  64
#define SEQ    2048
#define NBATCH 2
#define NTOK   (NBATCH * SEQ)   // 4096

// ---------------- scratch ----------------
__device__ float g_h  [(size_t)NTOK * DMODEL];
__device__ float g_q  [(size_t)NTOK * DMODEL];
__device__ float g_k  [(size_t)NTOK * DMODEL];
__device__ float g_v  [(size_t)NTOK * DMODEL];
__device__ float g_sc [(size_t)NBATCH * NHEADS * SEQ * SEQ]; // 512 MB
__device__ float g_att[(size_t)NTOK * DMODEL];
__device__ float g_x1 [(size_t)NTOK * DMODEL];
__device__ float g_h2 [(size_t)NTOK * DMODEL];
__device__ float g_ff [(size_t)NTOK * DFF];

// ---------------- helpers ----------------
__device__ __forceinline__ float warpSum(float v) {
    #pragma unroll
    for (int o = 16; o > 0; o >>= 1) v += __shfl_xor_sync(0xffffffffu, v, o);
    return v;
}
__device__ __forceinline__ float warpMax(float v) {
    #pragma unroll
    for (int o = 16; o > 0; o >>= 1) v = fmaxf(v, __shfl_xor_sync(0xffffffffu, v, o));
    return v;
}
__device__ __forceinline__ float gelu_f(float x) {
    const float c = 0.7978845608028654f;
    float x3 = x * x * x;
    return 0.5f * x * (1.0f + tanhf(c * (x + 0.044715f * x3)));
}
__device__ __forceinline__ void cpasync16(void* s, const void* g) {
    unsigned int sa = (unsigned int)__cvta_generic_to_shared(s);
    asm volatile("cp.async.cg.shared.global [%0], [%1], 16;\n" :: "r"(sa), "l"(g));
}
__device__ __forceinline__ void cp_commit() {
    asm volatile("cp.async.commit_group;\n");
}
template <int N>
__device__ __forceinline__ void cp_wait() {
    asm volatile("cp.async.wait_group %0;\n" :: "n"(N));
}

// ---------------- LayerNorm ----------------
__global__ void __launch_bounds__(256) ln_kernel(
    const float* __restrict__ X, const float* __restrict__ g,
    const float* __restrict__ b, float* __restrict__ Y)
{
    long row = blockIdx.x;
    const float* x = X + row * DMODEL;
    float v[4];
    float s = 0.f, s2 = 0.f;
    #pragma unroll
    for (int i = 0; i < 4; i++) {
        v[i] = x[threadIdx.x + i * 256];
        s += v[i]; s2 += v[i] * v[i];
    }
    s = warpSum(s); s2 = warpSum(s2);
    __shared__ float sh[2][8];
    int w = threadIdx.x >> 5, l = threadIdx.x & 31;
    if (l == 0) { sh[0][w] = s; sh[1][w] = s2; }
    __syncthreads();
    if (w == 0) {
        float a = (l < 8) ? sh[0][l] : 0.f;
        float c = (l < 8) ? sh[1][l] : 0.f;
        a = warpSum(a); c = warpSum(c);
        if (l == 0) { sh[0][0] = a; sh[1][0] = c; }
    }
    __syncthreads();
    float mean = sh[0][0] * (1.0f / DMODEL);
    float var  = sh[1][0] * (1.0f / DMODEL) - mean * mean;
    float rstd = rsqrtf(var + 1e-5f);
    #pragma unroll
    for (int i = 0; i < 4; i++) {
        int c = threadIdx.x + i * 256;
        Y[row * DMODEL + c] = (v[i] - mean) * rstd * g[c] + b[c];
    }
}

// ---------------- softmax (float4 IO) ----------------
__global__ void __launch_bounds__(256) softmax_kernel(float* __restrict__ S)
{
    long row = blockIdx.x;
    float* p = S + row * (long)SEQ;
    float4 v[2];
    float mx = -1e30f;
    #pragma unroll
    for (int i = 0; i < 2; i++) {
        v[i] = *(float4*)(p + (threadIdx.x + i * 256) * 4);
        mx = fmaxf(mx, fmaxf(fmaxf(v[i].x, v[i].y), fmaxf(v[i].z, v[i].w)));
    }
    mx = warpMax(mx);
    __shared__ float sh[8];
    int w = threadIdx.x >> 5, l = threadIdx.x & 31;
    if (l == 0) sh[w] = mx;
    __syncthreads();
    if (w == 0) {
        float a = (l < 8) ? sh[l] : -1e30f;
        a = warpMax(a);
        if (l == 0) sh[0] = a;
    }
    __syncthreads();
    mx = sh[0];
    __syncthreads();
    float sum = 0.f;
    #pragma unroll
    for (int i = 0; i < 2; i++) {
        v[i].x = expf(v[i].x - mx); v[i].y = expf(v[i].y - mx);
        v[i].z = expf(v[i].z - mx); v[i].w = expf(v[i].w - mx);
        sum += v[i].x + v[i].y + v[i].z + v[i].w;
    }
    sum = warpSum(sum);
    if (l == 0) sh[w] = sum;
    __syncthreads();
    if (w == 0) {
        float a = (l < 8) ? sh[l] : 0.f;
        a = warpSum(a);
        if (l == 0) sh[0] = a;
    }
    __syncthreads();
    float inv = 1.0f / sh[0];
    #pragma unroll
    for (int i = 0; i < 2; i++) {
        v[i].x *= inv; v[i].y *= inv; v[i].z *= inv; v[i].w *= inv;
        *(float4*)(p + (threadIdx.x + i * 256) * 4) = v[i];
    }
}

// ---------------- pipelined TF32 WMMA GEMM ----------------
// C[M,N] = alpha * A[M,K] @ op(B) (+bias)(+gelu)(+residual)
// TB=false: B is [K,N] row-major (ldb). TB=true: B is [N,K] row-major (ldb),
//           loaded as-is into smem and consumed as a col_major wmma fragment.
// epi: 0 none, 1 +bias, 2 gelu(x+bias), 3 x+bias+Res
#define BM 128
#define BK 16
#define NSTAGE 3
#define SAP 20            // BK + 4 pad
#define SCP 68            // epilogue pitch

template <int BNT, bool TB>
__global__ void __launch_bounds__(256) gemm_tf32(
    const float* __restrict__ A, const float* __restrict__ B,
    const float* __restrict__ bias, const float* __restrict__ Res,
    float* __restrict__ C,
    int M, int N, int K, int lda, int ldb, int ldc,
    int HH, long saH, long saL, long sbH, long sbL, long scH, long scL,
    float alpha, int epi)
{
    constexpr int SBP = TB ? SAP : (BNT + 4);
    constexpr int SA_FL = BM * SAP;                       // 2560
    constexpr int SB_FL = TB ? (BNT * SAP) : (BK * SBP);  // 2560 / 2112 / 1088
    constexpr int STAGE_FL = SA_FL + SB_FL;
    constexpr int WJ = BNT / 32;                          // frags per warp in N: 4 or 2
    constexpr int NPASS = (BNT == 128) ? 2 : 1;

    extern __shared__ float smem[];

    int z = blockIdx.z;
    A += (long)(z / HH) * saH + (long)(z % HH) * saL;
    B += (long)(z / HH) * sbH + (long)(z % HH) * sbL;
    C += (long)(z / HH) * scH + (long)(z % HH) * scL;

    const int m0 = blockIdx.y * BM;
    const int n0 = blockIdx.x * BNT;
    const int tid = threadIdx.x;
    const int wid = tid >> 5;
    const int wr = wid >> 1;      // 0..3
    const int wc = wid & 1;       // 0..1

    wmma::fragment<wmma::accumulator, 16, 16, 8, float> acc[2][WJ];
    #pragma unroll
    for (int i = 0; i < 2; i++)
        #pragma unroll
        for (int j = 0; j < WJ; j++)
            wmma::fill_fragment(acc[i][j], 0.0f);

    // ---- stage loader ----
    auto load_stage = [&](int s, int k) {
        float* sA = smem + s * STAGE_FL;
        float* sB = sA + SA_FL;
        // A: 512 float4, 2 per thread
        #pragma unroll
        for (int i = 0; i < 2; i++) {
            int f4 = tid + i * 256;
            int row = f4 >> 2, cq = f4 & 3;
            cpasync16(sA + row * SAP + cq * 4,
                      A + (long)(m0 + row) * lda + k + cq * 4);
        }
        if (TB) {
            // B tile from [N,K]: BNT rows x BK cols -> smem [BNT][SAP]
            #pragma unroll
            for (int i = 0; i < BNT * 4 / 256; i++) {
                int f4 = tid + i * 256;
                int nr = f4 >> 2, cq = f4 & 3;
                cpasync16(sB + nr * SAP + cq * 4,
                          B + (long)(n0 + nr) * ldb + k + cq * 4);
            }
        } else {
            // B tile from [K,N]: BK rows x BNT cols -> smem [BK][SBP]
            #pragma unroll
            for (int i = 0; i < BK * BNT / 4 / 256; i++) {
                int f4 = tid + i * 256;
                int row = f4 / (BNT / 4), cq = f4 % (BNT / 4);
                cpasync16(sB + row * SBP + cq * 4,
                          B + (long)(k + row) * ldb + n0 + cq * 4);
            }
        }
    };

    const int kt = K / BK;
    load_stage(0, 0); cp_commit();
    load_stage(1, BK); cp_commit();

    for (int it = 0; it < kt; it++) {
        cp_wait<1>();
        __syncthreads();
        // prefetch stage it+2 (overwrites stage it-1, safe after the sync)
        if (it + 2 < kt) load_stage((it + 2) % NSTAGE, (it + 2) * BK);
        cp_commit();

        const float* sA = smem + (it % NSTAGE) * STAGE_FL;
        const float* sB = sA + SA_FL;

        #pragma unroll
        for (int kk = 0; kk < BK; kk += 8) {
            wmma::fragment<wmma::matrix_a, 16, 16, 8, wmma::precision::tf32, wmma::row_major> af[2];
            #pragma unroll
            for (int i = 0; i < 2; i++) {
                wmma::load_matrix_sync(af[i], sA + (wr * 32 + i * 16) * SAP + kk, SAP);
                #pragma unroll
                for (int t = 0; t < af[i].num_elements; t++)
                    af[i].x[t] = wmma::__float_to_tf32(af[i].x[t]);
            }
            if (TB) {
                wmma::fragment<wmma::matrix_b, 16, 16, 8, wmma::precision::tf32, wmma::col_major> bf[WJ];
                #pragma unroll
                for (int j = 0; j < WJ; j++) {
                    wmma::load_matrix_sync(bf[j], sB + (wc * (BNT / 2) + j * 16) * SAP + kk, SAP);
                    #pragma unroll
                    for (int t = 0; t < bf[j].num_elements; t++)
                        bf[j].x[t] = wmma::__float_to_tf32(bf[j].x[t]);
                }
                #pragma unroll
                for (int i = 0; i < 2; i++)
                    #pragma unroll
                    for (int j = 0; j < WJ; j++)
                        wmma::mma_sync(acc[i][j], af[i], bf[j], acc[i][j]);
            } else {
                wmma::fragment<wmma::matrix_b, 16, 16, 8, wmma::precision::tf32, wmma::row_major> bf[WJ];
                #pragma unroll
                for (int j = 0; j < WJ; j++) {
                    wmma::load_matrix_sync(bf[j], sB + kk * SBP + wc * (BNT / 2) + j * 16, SBP);
                    #pragma unroll
                    for (int t = 0; t < bf[j].num_elements; t++)
                        bf[j].x[t] = wmma::__float_to_tf32(bf[j].x[t]);
                }
                #pragma unroll
                for (int i = 0; i < 2; i++)
                    #pragma unroll
                    for (int j = 0; j < WJ; j++)
                        wmma::mma_sync(acc[i][j], af[i], bf[j], acc[i][j]);
            }
        }
        __syncthreads();
    }

    // ---- epilogue: pass over 64-wide column halves through smem ----
    float* sC = smem;  // reuse
    #pragma unroll
    for (int p = 0; p < NPASS; p++) {
        if (NPASS == 1 || wc == p) {
            #pragma unroll
            for (int i = 0; i < 2; i++)
                #pragma unroll
                for (int j = 0; j < WJ; j++) {
                    int colLocal = (NPASS == 1 ? wc * 32 : 0) + j * 16;
                    wmma::store_matrix_sync(sC + (wr * 32 + i * 16) * SCP + colLocal,
                                            acc[i][j], SCP, wmma::mem_row_major);
                }
        }
        __syncthreads();
        #pragma unroll
        for (int i = 0; i < 8; i++) {
            int f4 = tid + i * 256;            // 0..2047
            int row = f4 >> 4, cq = f4 & 15;
            float4 vv = *(float4*)(sC + row * SCP + cq * 4);
            int gm = m0 + row, gn = n0 + p * 64 + cq * 4;
            float r[4] = {vv.x, vv.y, vv.z, vv.w};
            #pragma unroll
            for (int c2 = 0; c2 < 4; c2++) {
                float val = r[c2] * alpha;
                if (epi >= 1) val += bias[gn + c2];
                if (epi == 2) val = gelu_f(val);
                if (epi == 3) val += Res[(long)gm * ldc + gn + c2];
                r[c2] = val;
            }
            *(float4*)(C + (long)gm * ldc + gn) = make_float4(r[0], r[1], r[2], r[3]);
        }
        if (p + 1 < NPASS) __syncthreads();
    }
}

// ---------------- launch ----------------
extern "C" void kernel_launch(void* const* d_in, const int* in_sizes, int n_in,
                              void* d_out, int out_size)
{
    const float* x   = (const float*)d_in[0];
    const float* Wq  = (const float*)d_in[1];
    const float* bq  = (const float*)d_in[2];
    const float* Wk  = (const float*)d_in[3];
    const float* bk  = (const float*)d_in[4];
    const float* Wv  = (const float*)d_in[5];
    const float* bv  = (const float*)d_in[6];
    const float* Wp  = (const float*)d_in[7];
    const float* bp  = (const float*)d_in[8];
    const float* W1  = (const float*)d_in[9];
    const float* b1  = (const float*)d_in[10];
    const float* W2  = (const float*)d_in[11];
    const float* b2  = (const float*)d_in[12];
    const float* g1  = (const float*)d_in[13];
    const float* be1 = (const float*)d_in[14];
    const float* g2  = (const float*)d_in[15];
    const float* be2 = (const float*)d_in[16];
    float* out = (float*)d_out;

    float *h, *q, *k, *v, *sc, *att, *x1, *h2, *ff;
    cudaGetSymbolAddress((void**)&h,   g_h);
    cudaGetSymbolAddress((void**)&q,   g_q);
    cudaGetSymbolAddress((void**)&k,   g_k);
    cudaGetSymbolAddress((void**)&v,   g_v);
    cudaGetSymbolAddress((void**)&sc,  g_sc);
    cudaGetSymbolAddress((void**)&att, g_att);
    cudaGetSymbolAddress((void**)&x1,  g_x1);
    cudaGetSymbolAddress((void**)&h2,  g_h2);
    cudaGetSymbolAddress((void**)&ff,  g_ff);

    const long SD = (long)SEQ * DMODEL;
    const long SS = (long)SEQ * SEQ;

    // dynamic smem sizes
    const int smem128f = NSTAGE * (BM * SAP + BK * 132) * 4;   // 56064
    const int smem128t = NSTAGE * (BM * SAP + 128 * SAP) * 4;  // 61440
    const int smem64f  = NSTAGE * (BM * SAP + BK * 68) * 4;    // 43776
    static bool attr_done = false;
    if (!attr_done) {
        cudaFuncSetAttribute(gemm_tf32<128, false>,
            cudaFuncAttributeMaxDynamicSharedMemorySize, smem128f);
        cudaFuncSetAttribute(gemm_tf32<128, true>,
            cudaFuncAttributeMaxDynamicSharedMemorySize, smem128t);
        cudaFuncSetAttribute(gemm_tf32<64, false>,
            cudaFuncAttributeMaxDynamicSharedMemorySize, smem64f);
        attr_done = true;
    }

    // 1) LN1
    ln_kernel<<<NTOK, 256>>>(x, g1, be1, h);

    // 2) Q, K, V projections
    dim3 gProj(DMODEL / 128, NTOK / BM, 1);
    gemm_tf32<128, false><<<gProj, 256, smem128f>>>(h, Wq, bq, nullptr, q,
        NTOK, DMODEL, DMODEL, DMODEL, DMODEL, DMODEL,
        1, 0, 0, 0, 0, 0, 0, 1.0f, 1);
    gemm_tf32<128, false><<<gProj, 256, smem128f>>>(h, Wk, bk, nullptr, k,
        NTOK, DMODEL, DMODEL, DMODEL, DMODEL, DMODEL,
        1, 0, 0, 0, 0, 0, 0, 1.0f, 1);
    gemm_tf32<128, false><<<gProj, 256, smem128f>>>(h, Wv, bv, nullptr, v,
        NTOK, DMODEL, DMODEL, DMODEL, DMODEL, DMODEL,
        1, 0, 0, 0, 0, 0, 0, 1.0f, 1);

    // 3) scores = Q @ K^T / 8 (batched over 32 (b,h))
    dim3 gScores(SEQ / 128, SEQ / BM, NBATCH * NHEADS);
    gemm_tf32<128, true><<<gScores, 256, smem128t>>>(q, k, nullptr, nullptr, sc,
        SEQ, SEQ, HEADD, DMODEL, DMODEL, SEQ,
        NHEADS, SD, HEADD, SD, HEADD, (long)NHEADS * SS, SS,
        0.125f, 0);

    // 4) softmax
    softmax_kernel<<<NBATCH * NHEADS * SEQ, 256>>>(sc);

    // 5) attn_out = scores @ V
    dim3 gAV(HEADD / 64, SEQ / BM, NBATCH * NHEADS);
    gemm_tf32<64, false><<<gAV, 256, smem64f>>>(sc, v, nullptr, nullptr, att,
        SEQ, HEADD, SEQ, SEQ, DMODEL, DMODEL,
        NHEADS, (long)NHEADS * SS, SS, SD, HEADD, SD, HEADD,
        1.0f, 0);

    // 6) x1 = x + attn_out @ Wp + bp
    gemm_tf32<128, false><<<gProj, 256, smem128f>>>(att, Wp, bp, x, x1,
        NTOK, DMODEL, DMODEL, DMODEL, DMODEL, DMODEL,
        1, 0, 0, 0, 0, 0, 0, 1.0f, 3);

    // 7) LN2
    ln_kernel<<<NTOK, 256>>>(x1, g2, be2, h2);

    // 8) ff = gelu(h2 @ W1 + b1)
    dim3 gFF1(DFF / 128, NTOK / BM, 1);
    gemm_tf32<128, false><<<gFF1, 256, smem128f>>>(h2, W1, b1, nullptr, ff,
        NTOK, DFF, DMODEL, DMODEL, DFF, DFF,
        1, 0, 0, 0, 0, 0, 0, 1.0f, 2);

    // 9) out = x1 + ff @ W2 + b2
    dim3 gFF2(DMODEL / 128, NTOK / BM, 1);
    gemm_tf32<128, false><<<gFF2, 256, smem128f>>>(ff, W2, b2, x1, out,
        NTOK, DMODEL, DFF, DFF, DMODEL, DMODEL,
        1, 0, 0, 0, 0, 0, 0, 1.0f, 3);
}

// round 5
// speedup vs baseline: 1.8403x; 1.8403x over previous
#include <cuda_runtime.h>
#include <math.h>
#include <cstdint>
#include <cstddef>

#define DMODEL 1024
#define DFF    4096
#define NHEADS 16
#define HEADD  64
#define SEQ    2048
#define NBATCH 2
#define NTOK   (NBATCH * SEQ)   // 4096

// ---------------- scratch ----------------
__device__ float g_h  [(size_t)NTOK * DMODEL];
__device__ float g_q  [(size_t)NTOK * DMODEL];
__device__ float g_k  [(size_t)NTOK * DMODEL];
__device__ float g_v  [(size_t)NTOK * DMODEL];
__device__ float g_sc [(size_t)NBATCH * NHEADS * SEQ * SEQ]; // 512 MB
__device__ float g_att[(size_t)NTOK * DMODEL];
__device__ float g_x1 [(size_t)NTOK * DMODEL];
__device__ float g_h2 [(size_t)NTOK * DMODEL];
__device__ float g_ff [(size_t)NTOK * DFF];
__device__ float g_wq [(size_t)DMODEL * DMODEL];
__device__ float g_wk [(size_t)DMODEL * DMODEL];
__device__ float g_wv [(size_t)DMODEL * DMODEL];
__device__ float g_wp [(size_t)DMODEL * DMODEL];
__device__ float g_w1 [(size_t)DMODEL * DFF];
__device__ float g_w2 [(size_t)DFF * DMODEL];

// ---------------- helpers ----------------
__device__ __forceinline__ float warpSum(float v) {
    #pragma unroll
    for (int o = 16; o > 0; o >>= 1) v += __shfl_xor_sync(0xffffffffu, v, o);
    return v;
}
__device__ __forceinline__ float warpMax(float v) {
    #pragma unroll
    for (int o = 16; o > 0; o >>= 1) v = fmaxf(v, __shfl_xor_sync(0xffffffffu, v, o));
    return v;
}
__device__ __forceinline__ float gelu_f(float x) {
    const float c = 0.7978845608028654f;
    float x3 = x * x * x;
    return 0.5f * x * (1.0f + tanhf(c * (x + 0.044715f * x3)));
}
__device__ __forceinline__ float rn_tf32(float x) {
    unsigned u;
    asm("cvt.rna.tf32.f32 %0, %1;" : "=r"(u) : "f"(x));
    return __uint_as_float(u);
}
__device__ __forceinline__ void cpasync16(void* s, const void* g) {
    unsigned int sa = (unsigned int)__cvta_generic_to_shared(s);
    asm volatile("cp.async.cg.shared.global [%0], [%1], 16;\n" :: "r"(sa), "l"(g));
}
__device__ __forceinline__ void cp_commit() {
    asm volatile("cp.async.commit_group;\n");
}
template <int N>
__device__ __forceinline__ void cp_wait() {
    asm volatile("cp.async.wait_group %0;\n" :: "n"(N));
}
__device__ __forceinline__ void mma_tf32(float* c, const uint32_t* a, const uint32_t* b) {
    asm volatile(
        "mma.sync.aligned.m16n8k8.row.col.f32.tf32.tf32.f32 "
        "{%0,%1,%2,%3}, {%4,%5,%6,%7}, {%8,%9}, {%0,%1,%2,%3};\n"
        : "+f"(c[0]), "+f"(c[1]), "+f"(c[2]), "+f"(c[3])
        : "r"(a[0]), "r"(a[1]), "r"(a[2]), "r"(a[3]), "r"(b[0]), "r"(b[1]));
}

// ---------------- weight round-copy (tf32) ----------------
__global__ void __launch_bounds__(256) roundcopy(
    const float* __restrict__ in, float* __restrict__ out)
{
    long i = ((long)blockIdx.x * 256 + threadIdx.x) * 4;
    float4 v = *(const float4*)(in + i);
    v.x = rn_tf32(v.x); v.y = rn_tf32(v.y);
    v.z = rn_tf32(v.z); v.w = rn_tf32(v.w);
    *(float4*)(out + i) = v;
}

// ---------------- LayerNorm (tf32-rounded output) ----------------
__global__ void __launch_bounds__(256) ln_kernel(
    const float* __restrict__ X, const float* __restrict__ g,
    const float* __restrict__ b, float* __restrict__ Y)
{
    long row = blockIdx.x;
    const float* x = X + row * DMODEL;
    float v[4];
    float s = 0.f, s2 = 0.f;
    #pragma unroll
    for (int i = 0; i < 4; i++) {
        v[i] = x[threadIdx.x + i * 256];
        s += v[i]; s2 += v[i] * v[i];
    }
    s = warpSum(s); s2 = warpSum(s2);
    __shared__ float sh[2][8];
    int w = threadIdx.x >> 5, l = threadIdx.x & 31;
    if (l == 0) { sh[0][w] = s; sh[1][w] = s2; }
    __syncthreads();
    if (w == 0) {
        float a = (l < 8) ? sh[0][l] : 0.f;
        float c = (l < 8) ? sh[1][l] : 0.f;
        a = warpSum(a); c = warpSum(c);
        if (l == 0) { sh[0][0] = a; sh[1][0] = c; }
    }
    __syncthreads();
    float mean = sh[0][0] * (1.0f / DMODEL);
    float var  = sh[1][0] * (1.0f / DMODEL) - mean * mean;
    float rstd = rsqrtf(var + 1e-5f);
    #pragma unroll
    for (int i = 0; i < 4; i++) {
        int c = threadIdx.x + i * 256;
        Y[row * DMODEL + c] = rn_tf32((v[i] - mean) * rstd * g[c] + b[c]);
    }
}

// ---------------- softmax (tf32-rounded output) ----------------
__global__ void __launch_bounds__(256) softmax_kernel(float* __restrict__ S)
{
    long row = blockIdx.x;
    float* p = S + row * (long)SEQ;
    float4 v[2];
    float mx = -1e30f;
    #pragma unroll
    for (int i = 0; i < 2; i++) {
        v[i] = *(float4*)(p + (threadIdx.x + i * 256) * 4);
        mx = fmaxf(mx, fmaxf(fmaxf(v[i].x, v[i].y), fmaxf(v[i].z, v[i].w)));
    }
    mx = warpMax(mx);
    __shared__ float sh[8];
    int w = threadIdx.x >> 5, l = threadIdx.x & 31;
    if (l == 0) sh[w] = mx;
    __syncthreads();
    if (w == 0) {
        float a = (l < 8) ? sh[l] : -1e30f;
        a = warpMax(a);
        if (l == 0) sh[0] = a;
    }
    __syncthreads();
    mx = sh[0];
    __syncthreads();
    float sum = 0.f;
    #pragma unroll
    for (int i = 0; i < 2; i++) {
        v[i].x = expf(v[i].x - mx); v[i].y = expf(v[i].y - mx);
        v[i].z = expf(v[i].z - mx); v[i].w = expf(v[i].w - mx);
        sum += v[i].x + v[i].y + v[i].z + v[i].w;
    }
    sum = warpSum(sum);
    if (l == 0) sh[w] = sum;
    __syncthreads();
    if (w == 0) {
        float a = (l < 8) ? sh[l] : 0.f;
        a = warpSum(a);
        if (l == 0) sh[0] = a;
    }
    __syncthreads();
    float inv = 1.0f / sh[0];
    #pragma unroll
    for (int i = 0; i < 2; i++) {
        v[i].x = rn_tf32(v[i].x * inv); v[i].y = rn_tf32(v[i].y * inv);
        v[i].z = rn_tf32(v[i].z * inv); v[i].w = rn_tf32(v[i].w * inv);
        *(float4*)(p + (threadIdx.x + i * 256) * 4) = v[i];
    }
}

// ---------------- raw-mma TF32 GEMM ----------------
// C[M,N] = alpha * A[M,K] @ op(B) (+epi).  A: [M,K] row-major, lda.
// TB=false: B [K,N] row-major (ldb).  TB=true: B [N,K] row-major (ldb).
// Inputs MUST be tf32-pre-rounded (mma truncates; exact for pre-rounded data).
// epi bits: 1=+bias, 2=gelu, 4=+Res, 8=round output to tf32
#define BM 128
#define BKG 16
#define NS 3
#define SAP 20      // A smem pitch (floats)

template <int BN, bool TB>
__global__ void __launch_bounds__(256) mma_gemm(
    const float* __restrict__ A, const float* __restrict__ B,
    const float* __restrict__ bias, const float* __restrict__ Res,
    float* __restrict__ C,
    int K, int lda, int ldb, int ldc,
    int HH, long saH, long saL, long sbH, long sbL, long scH, long scL,
    float alpha, int epi)
{
    constexpr int WM = (BN == 128) ? 64 : 32;     // warp tile M
    constexpr int MF = WM / 16;                    // 4 or 2
    constexpr int NF = 4;                          // warp tile N = 32 = 4x8
    constexpr int NWX = BN / 32;                   // warps along N: 4 or 2
    constexpr int SBP = TB ? SAP : (BN + 8);       // B smem pitch
    constexpr int SAF = BM * SAP;                  // A stage floats = 2560
    constexpr int SBF = TB ? (BN * SAP) : (BKG * SBP);
    constexpr int STG = SAF + SBF;

    extern __shared__ float smem[];

    int z = blockIdx.z;
    A += (long)(z / HH) * saH + (long)(z % HH) * saL;
    B += (long)(z / HH) * sbH + (long)(z % HH) * sbL;
    C += (long)(z / HH) * scH + (long)(z % HH) * scL;
    const int m0 = blockIdx.y * BM;
    const int n0 = blockIdx.x * BN;
    const int tid = threadIdx.x;
    const int wid = tid >> 5, lane = tid & 31;
    const int wmI = wid / NWX, wnI = wid % NWX;
    const int g = lane >> 2, t4 = lane & 3;

    float acc[MF][NF][4];
    #pragma unroll
    for (int i = 0; i < MF; i++)
        #pragma unroll
        for (int j = 0; j < NF; j++)
            #pragma unroll
            for (int u = 0; u < 4; u++) acc[i][j][u] = 0.f;

    auto load_stage = [&](int s, int k0) {
        float* sA = smem + s * STG;
        float* sB = sA + SAF;
        #pragma unroll
        for (int i = 0; i < 2; i++) {           // A: 128x16 = 512 chunks
            int ch = tid + i * 256;
            int row = ch >> 2, c4 = ch & 3;
            cpasync16(sA + row * SAP + c4 * 4,
                      A + (long)(m0 + row) * lda + k0 + c4 * 4);
        }
        if (TB) {
            #pragma unroll
            for (int i = 0; i < BN * 4 / 256; i++) {   // BNx16
                int ch = tid + i * 256;
                int row = ch >> 2, c4 = ch & 3;
                cpasync16(sB + row * SAP + c4 * 4,
                          B + (long)(n0 + row) * ldb + k0 + c4 * 4);
            }
        } else {
            #pragma unroll
            for (int i = 0; i < BKG * BN / 4 / 256; i++) {  // 16xBN
                int ch = tid + i * 256;
                int row = ch / (BN / 4), c4 = ch % (BN / 4);
                cpasync16(sB + row * SBP + c4 * 4,
                          B + (long)(k0 + row) * ldb + n0 + c4 * 4);
            }
        }
    };

    const int kt = K / BKG;
    load_stage(0, 0);       cp_commit();
    load_stage(1, BKG);     cp_commit();

    for (int it = 0; it < kt; it++) {
        cp_wait<1>();
        __syncthreads();
        if (it + 2 < kt) load_stage((it + 2) % NS, (it + 2) * BKG);
        cp_commit();

        const float* sA = smem + (it % NS) * STG;
        const float* sB = sA + SAF;

        #pragma unroll
        for (int kk = 0; kk < BKG; kk += 8) {
            uint32_t af[MF][4], bf[NF][2];
            #pragma unroll
            for (int mf = 0; mf < MF; mf++) {
                int r = wmI * WM + mf * 16 + g;
                af[mf][0] = __float_as_uint(sA[r * SAP + kk + t4]);
                af[mf][1] = __float_as_uint(sA[(r + 8) * SAP + kk + t4]);
                af[mf][2] = __float_as_uint(sA[r * SAP + kk + t4 + 4]);
                af[mf][3] = __float_as_uint(sA[(r + 8) * SAP + kk + t4 + 4]);
            }
            #pragma unroll
            for (int nf = 0; nf < NF; nf++) {
                int n = wnI * 32 + nf * 8 + g;
                if (TB) {
                    bf[nf][0] = __float_as_uint(sB[n * SAP + kk + t4]);
                    bf[nf][1] = __float_as_uint(sB[n * SAP + kk + t4 + 4]);
                } else {
                    bf[nf][0] = __float_as_uint(sB[(kk + t4) * SBP + n]);
                    bf[nf][1] = __float_as_uint(sB[(kk + t4 + 4) * SBP + n]);
                }
            }
            #pragma unroll
            for (int mf = 0; mf < MF; mf++)
                #pragma unroll
                for (int nf = 0; nf < NF; nf++)
                    mma_tf32(acc[mf][nf], af[mf], bf[nf]);
        }
        __syncthreads();
    }

    // ---- register-direct epilogue ----
    #pragma unroll
    for (int nf = 0; nf < NF; nf++) {
        int col = n0 + wnI * 32 + nf * 8 + t4 * 2;
        float b0 = 0.f, b1 = 0.f;
        if (epi & 1) { b0 = bias[col]; b1 = bias[col + 1]; }
        #pragma unroll
        for (int mf = 0; mf < MF; mf++) {
            int row0 = m0 + wmI * WM + mf * 16 + g;
            #pragma unroll
            for (int hh = 0; hh < 2; hh++) {
                long rr = row0 + hh * 8;
                float v0 = acc[mf][nf][hh * 2] * alpha + b0;
                float v1 = acc[mf][nf][hh * 2 + 1] * alpha + b1;
                if (epi & 2) { v0 = gelu_f(v0); v1 = gelu_f(v1); }
                if (epi & 4) {
                    v0 += Res[rr * ldc + col];
                    v1 += Res[rr * ldc + col + 1];
                }
                if (epi & 8) { v0 = rn_tf32(v0); v1 = rn_tf32(v1); }
                *(float2*)(C + rr * ldc + col) = make_float2(v0, v1);
            }
        }
    }
}

// ---------------- launch ----------------
extern "C" void kernel_launch(void* const* d_in, const int* in_sizes, int n_in,
                              void* d_out, int out_size)
{
    const float* x   = (const float*)d_in[0];
    const float* Wq  = (const float*)d_in[1];
    const float* bq  = (const float*)d_in[2];
    const float* Wk  = (const float*)d_in[3];
    const float* bk  = (const float*)d_in[4];
    const float* Wv  = (const float*)d_in[5];
    const float* bv  = (const float*)d_in[6];
    const float* Wp  = (const float*)d_in[7];
    const float* bp  = (const float*)d_in[8];
    const float* W1  = (const float*)d_in[9];
    const float* b1  = (const float*)d_in[10];
    const float* W2  = (const float*)d_in[11];
    const float* b2  = (const float*)d_in[12];
    const float* g1  = (const float*)d_in[13];
    const float* be1 = (const float*)d_in[14];
    const float* g2  = (const float*)d_in[15];
    const float* be2 = (const float*)d_in[16];
    float* out = (float*)d_out;

    float *h, *q, *k, *v, *sc, *att, *x1, *h2, *ff;
    float *wq, *wk, *wv, *wp, *w1, *w2;
    cudaGetSymbolAddress((void**)&h,   g_h);
    cudaGetSymbolAddress((void**)&q,   g_q);
    cudaGetSymbolAddress((void**)&k,   g_k);
    cudaGetSymbolAddress((void**)&v,   g_v);
    cudaGetSymbolAddress((void**)&sc,  g_sc);
    cudaGetSymbolAddress((void**)&att, g_att);
    cudaGetSymbolAddress((void**)&x1,  g_x1);
    cudaGetSymbolAddress((void**)&h2,  g_h2);
    cudaGetSymbolAddress((void**)&ff,  g_ff);
    cudaGetSymbolAddress((void**)&wq,  g_wq);
    cudaGetSymbolAddress((void**)&wk,  g_wk);
    cudaGetSymbolAddress((void**)&wv,  g_wv);
    cudaGetSymbolAddress((void**)&wp,  g_wp);
    cudaGetSymbolAddress((void**)&w1,  g_w1);
    cudaGetSymbolAddress((void**)&w2,  g_w2);

    const long SD = (long)SEQ * DMODEL;
    const long SS = (long)SEQ * SEQ;

    const int smem128f = NS * (BM * SAP + BKG * 136) * 4;  // 56832
    const int smem128t = NS * (BM * SAP + 128 * SAP) * 4;  // 61440
    const int smem64f  = NS * (BM * SAP + BKG * 72) * 4;   // 44544
    static bool attr_done = false;
    if (!attr_done) {
        cudaFuncSetAttribute(mma_gemm<128, false>,
            cudaFuncAttributeMaxDynamicSharedMemorySize, smem128f);
        cudaFuncSetAttribute(mma_gemm<128, true>,
            cudaFuncAttributeMaxDynamicSharedMemorySize, smem128t);
        cudaFuncSetAttribute(mma_gemm<64, false>,
            cudaFuncAttributeMaxDynamicSharedMemorySize, smem64f);
        attr_done = true;
    }

    // 0) round weights to tf32
    roundcopy<<<DMODEL * DMODEL / 1024, 256>>>(Wq, wq);
    roundcopy<<<DMODEL * DMODEL / 1024, 256>>>(Wk, wk);
    roundcopy<<<DMODEL * DMODEL / 1024, 256>>>(Wv, wv);
    roundcopy<<<DMODEL * DMODEL / 1024, 256>>>(Wp, wp);
    roundcopy<<<DMODEL * DFF / 1024, 256>>>(W1, w1);
    roundcopy<<<DMODEL * DFF / 1024, 256>>>(W2, w2);

    // 1) LN1
    ln_kernel<<<NTOK, 256>>>(x, g1, be1, h);

    // 2) Q, K, V projections (bias + round)
    dim3 gProj(DMODEL / 128, NTOK / BM, 1);
    mma_gemm<128, false><<<gProj, 256, smem128f>>>(h, wq, bq, nullptr, q,
        DMODEL, DMODEL, DMODEL, DMODEL, 1, 0, 0, 0, 0, 0, 0, 1.0f, 1 | 8);
    mma_gemm<128, false><<<gProj, 256, smem128f>>>(h, wk, bk, nullptr, k,
        DMODEL, DMODEL, DMODEL, DMODEL, 1, 0, 0, 0, 0, 0, 0, 1.0f, 1 | 8);
    mma_gemm<128, false><<<gProj, 256, smem128f>>>(h, wv, bv, nullptr, v,
        DMODEL, DMODEL, DMODEL, DMODEL, 1, 0, 0, 0, 0, 0, 0, 1.0f, 1 | 8);

    // 3) scores = Q @ K^T / 8, batched over (b,h)=32
    dim3 gScores(SEQ / 128, SEQ / BM, NBATCH * NHEADS);
    mma_gemm<128, true><<<gScores, 256, smem128t>>>(q, k, nullptr, nullptr, sc,
        HEADD, DMODEL, DMODEL, SEQ,
        NHEADS, SD, HEADD, SD, HEADD, (long)NHEADS * SS, SS,
        0.125f, 0);

    // 4) softmax (rounds)
    softmax_kernel<<<NBATCH * NHEADS * SEQ, 256>>>(sc);

    // 5) attn_out = P @ V (round), per-head N=64
    dim3 gAV(1, SEQ / BM, NBATCH * NHEADS);
    mma_gemm<64, false><<<gAV, 256, smem64f>>>(sc, v, nullptr, nullptr, att,
        SEQ, SEQ, DMODEL, DMODEL,
        NHEADS, (long)NHEADS * SS, SS, SD, HEADD, SD, HEADD,
        1.0f, 8);

    // 6) x1 = x + att @ Wp + bp  (fp32)
    mma_gemm<128, false><<<gProj, 256, smem128f>>>(att, wp, bp, x, x1,
        DMODEL, DMODEL, DMODEL, DMODEL, 1, 0, 0, 0, 0, 0, 0, 1.0f, 1 | 4);

    // 7) LN2
    ln_kernel<<<NTOK, 256>>>(x1, g2, be2, h2);

    // 8) ff = gelu(h2 @ W1 + b1) (round)
    dim3 gFF1(DFF / 128, NTOK / BM, 1);
    mma_gemm<128, false><<<gFF1, 256, smem128f>>>(h2, w1, b1, nullptr, ff,
        DMODEL, DMODEL, DFF, DFF, 1, 0, 0, 0, 0, 0, 0, 1.0f, 1 | 2 | 8);

    // 9) out = x1 + ff @ W2 + b2  (fp32)
    dim3 gFF2(DMODEL / 128, NTOK / BM, 1);
    mma_gemm<128, false><<<gFF2, 256, smem128f>>>(ff, w2, b2, x1, out,
        DFF, DFF, DMODEL, DMODEL, 1, 0, 0, 0, 0, 0, 0, 1.0f, 1 | 4);
}

// round 6
// speedup vs baseline: 3.4447x; 1.8719x over previous
#include <cuda_runtime.h>
#include <cuda_fp16.h>
#include <math.h>
#include <cstdint>
#include <cstddef>

#define DMODEL 1024
#define DFF    4096
#define NHEADS 16
#define HEADD  64
#define SEQ    2048
#define NBATCH 2
#define NTOK   (NBATCH * SEQ)   // 4096

// ---------------- scratch ----------------
__device__ __half g_h  [(size_t)NTOK * DMODEL];
__device__ __half g_q  [(size_t)NTOK * DMODEL];
__device__ __half g_k  [(size_t)NTOK * DMODEL];
__device__ float  g_v  [(size_t)NTOK * DMODEL];   // fp32 (tf32-rounded) for PV mma
__device__ __half g_att[(size_t)NTOK * DMODEL];
__device__ float  g_x1 [(size_t)NTOK * DMODEL];
__device__ __half g_h2 [(size_t)NTOK * DMODEL];
__device__ __half g_ff [(size_t)NTOK * DFF];
// weights, transposed to K-major [N][K], fp16
__device__ __half g_wq [(size_t)DMODEL * DMODEL];
__device__ __half g_wk [(size_t)DMODEL * DMODEL];
__device__ __half g_wv [(size_t)DMODEL * DMODEL];
__device__ __half g_wp [(size_t)DMODEL * DMODEL];
__device__ __half g_w1 [(size_t)DFF * DMODEL];
__device__ __half g_w2 [(size_t)DMODEL * DFF];

// ---------------- helpers ----------------
__device__ __forceinline__ float warpSum(float v) {
    #pragma unroll
    for (int o = 16; o > 0; o >>= 1) v += __shfl_xor_sync(0xffffffffu, v, o);
    return v;
}
__device__ __forceinline__ float gelu_f(float x) {
    const float c = 0.7978845608028654f;
    float x3 = x * x * x;
    return 0.5f * x * (1.0f + tanhf(c * (x + 0.044715f * x3)));
}
__device__ __forceinline__ float rn_tf32(float x) {
    unsigned u;
    asm("cvt.rna.tf32.f32 %0, %1;" : "=r"(u) : "f"(x));
    return __uint_as_float(u);
}
__device__ __forceinline__ void cpasync16(void* s, const void* g) {
    unsigned int sa = (unsigned int)__cvta_generic_to_shared(s);
    asm volatile("cp.async.cg.shared.global [%0], [%1], 16;\n" :: "r"(sa), "l"(g));
}
__device__ __forceinline__ void cp_commit() {
    asm volatile("cp.async.commit_group;\n");
}
template <int N>
__device__ __forceinline__ void cp_wait() {
    asm volatile("cp.async.wait_group %0;\n" :: "n"(N));
}
__device__ __forceinline__ void mma_f16(float* c, const uint32_t* a, uint32_t b0, uint32_t b1) {
    asm volatile(
        "mma.sync.aligned.m16n8k16.row.col.f32.f16.f16.f32 "
        "{%0,%1,%2,%3}, {%4,%5,%6,%7}, {%8,%9}, {%0,%1,%2,%3};\n"
        : "+f"(c[0]), "+f"(c[1]), "+f"(c[2]), "+f"(c[3])
        : "r"(a[0]), "r"(a[1]), "r"(a[2]), "r"(a[3]), "r"(b0), "r"(b1));
}
__device__ __forceinline__ void mma_tf32(float* c, const uint32_t* a, uint32_t b0, uint32_t b1) {
    asm volatile(
        "mma.sync.aligned.m16n8k8.row.col.f32.tf32.tf32.f32 "
        "{%0,%1,%2,%3}, {%4,%5,%6,%7}, {%8,%9}, {%0,%1,%2,%3};\n"
        : "+f"(c[0]), "+f"(c[1]), "+f"(c[2]), "+f"(c[3])
        : "r"(a[0]), "r"(a[1]), "r"(a[2]), "r"(a[3]), "r"(b0), "r"(b1));
}

// ---------------- weight transpose fp32[K][N] -> fp16[N][K] ----------------
__global__ void __launch_bounds__(256) wtrans(
    const float* __restrict__ in, __half* __restrict__ out, int K, int N)
{
    __shared__ float t[32][33];
    int n0 = blockIdx.x * 32, k0 = blockIdx.y * 32;
    int tx = threadIdx.x, ty = threadIdx.y;
    #pragma unroll
    for (int i = ty; i < 32; i += 8)
        t[i][tx] = in[(long)(k0 + i) * N + n0 + tx];
    __syncthreads();
    #pragma unroll
    for (int i = ty; i < 32; i += 8)
        out[(long)(n0 + i) * K + k0 + tx] = __float2half_rn(t[tx][i]);
}

// ---------------- LayerNorm: fp32 in -> fp16 out ----------------
__global__ void __launch_bounds__(256) ln_kernel(
    const float* __restrict__ X, const float* __restrict__ g,
    const float* __restrict__ b, __half* __restrict__ Y)
{
    long row = blockIdx.x;
    int tid = threadIdx.x;
    const float* x = X + row * DMODEL;
    float4 xv = *(const float4*)(x + tid * 4);
    float s  = xv.x + xv.y + xv.z + xv.w;
    float s2 = xv.x * xv.x + xv.y * xv.y + xv.z * xv.z + xv.w * xv.w;
    s = warpSum(s); s2 = warpSum(s2);
    __shared__ float sh[2][8];
    int w = tid >> 5, l = tid & 31;
    if (l == 0) { sh[0][w] = s; sh[1][w] = s2; }
    __syncthreads();
    if (w == 0) {
        float a = (l < 8) ? sh[0][l] : 0.f;
        float c = (l < 8) ? sh[1][l] : 0.f;
        a = warpSum(a); c = warpSum(c);
        if (l == 0) { sh[0][0] = a; sh[1][0] = c; }
    }
    __syncthreads();
    float mean = sh[0][0] * (1.0f / DMODEL);
    float var  = sh[1][0] * (1.0f / DMODEL) - mean * mean;
    float rstd = rsqrtf(var + 1e-5f);
    float4 gv = *(const float4*)(g + tid * 4);
    float4 bv = *(const float4*)(b + tid * 4);
    float v0 = (xv.x - mean) * rstd * gv.x + bv.x;
    float v1 = (xv.y - mean) * rstd * gv.y + bv.y;
    float v2 = (xv.z - mean) * rstd * gv.z + bv.z;
    float v3 = (xv.w - mean) * rstd * gv.w + bv.w;
    __half2 h0 = __floats2half2_rn(v0, v1);
    __half2 h1 = __floats2half2_rn(v2, v3);
    uint2 u;
    u.x = *(uint32_t*)&h0; u.y = *(uint32_t*)&h1;
    *(uint2*)(Y + row * DMODEL + tid * 4) = u;
}

// ---------------- fp16 GEMM: C[M,N] = A[M,K]@Bt[N,K]^T + epi ----------------
// A fp16 row-major (lda), Bt fp16 K-major (ldb). CT = __half or float.
// epi: 1=+bias, 2=gelu, 4=+Res(fp32, ldc), 8=tf32-round (float out only)
#define PAH 40     // smem pitch in halves (80B)

template <typename CT>
__global__ void __launch_bounds__(256) hgemm(
    const __half* __restrict__ A, const __half* __restrict__ B,
    const float* __restrict__ bias, const float* __restrict__ Res,
    CT* __restrict__ C, int K, int lda, int ldb, int ldc, int epi)
{
    constexpr int STGB = 2 * 128 * PAH * 2;   // A+B per stage bytes = 20480
    extern __shared__ char smem[];

    const int m0 = blockIdx.y * 128;
    const int n0 = blockIdx.x * 128;
    const int tid = threadIdx.x;
    const int wid = tid >> 5, lane = tid & 31;
    const int wmI = wid >> 2, wnI = wid & 3;   // 2x4 warps, warp tile 64x32
    const int g = lane >> 2, t4 = lane & 3;

    float acc[4][4][4];
    #pragma unroll
    for (int i = 0; i < 4; i++)
        #pragma unroll
        for (int j = 0; j < 4; j++)
            #pragma unroll
            for (int u = 0; u < 4; u++) acc[i][j][u] = 0.f;

    auto load_stage = [&](int s, int k0) {
        char* st = smem + s * STGB;
        #pragma unroll
        for (int i = 0; i < 2; i++) {            // A: 128 rows x 4 chunks
            int ch = tid + i * 256;
            int row = ch >> 2, c = ch & 3;
            cpasync16(st + row * 80 + c * 16,
                      A + (long)(m0 + row) * lda + k0 + c * 8);
        }
        char* stB = st + 128 * 80;
        #pragma unroll
        for (int i = 0; i < 2; i++) {            // B: 128 rows x 4 chunks
            int ch = tid + i * 256;
            int row = ch >> 2, c = ch & 3;
            cpasync16(stB + row * 80 + c * 16,
                      B + (long)(n0 + row) * ldb + k0 + c * 8);
        }
    };

    const int kt = K / 32;
    load_stage(0, 0);  cp_commit();
    load_stage(1, 32); cp_commit();

    for (int it = 0; it < kt; it++) {
        cp_wait<1>();
        __syncthreads();
        if (it + 2 < kt) load_stage((it + 2) % 3, (it + 2) * 32);
        cp_commit();

        const __half* sA = (const __half*)(smem + (it % 3) * STGB);
        const __half* sB = sA + 128 * PAH;

        #pragma unroll
        for (int kk = 0; kk < 32; kk += 16) {
            uint32_t af[4][4], bf[4][2];
            #pragma unroll
            for (int mf = 0; mf < 4; mf++) {
                int r = wmI * 64 + mf * 16 + g;
                af[mf][0] = *(const uint32_t*)(sA + r * PAH + kk + 2 * t4);
                af[mf][1] = *(const uint32_t*)(sA + (r + 8) * PAH + kk + 2 * t4);
                af[mf][2] = *(const uint32_t*)(sA + r * PAH + kk + 2 * t4 + 8);
                af[mf][3] = *(const uint32_t*)(sA + (r + 8) * PAH + kk + 2 * t4 + 8);
            }
            #pragma unroll
            for (int nf = 0; nf < 4; nf++) {
                int n = wnI * 32 + nf * 8 + g;
                bf[nf][0] = *(const uint32_t*)(sB + n * PAH + kk + 2 * t4);
                bf[nf][1] = *(const uint32_t*)(sB + n * PAH + kk + 2 * t4 + 8);
            }
            #pragma unroll
            for (int mf = 0; mf < 4; mf++)
                #pragma unroll
                for (int nf = 0; nf < 4; nf++)
                    mma_f16(acc[mf][nf], af[mf], bf[nf][0], bf[nf][1]);
        }
        __syncthreads();
    }

    // ---- epilogue ----
    #pragma unroll
    for (int nf = 0; nf < 4; nf++) {
        int col = n0 + wnI * 32 + nf * 8 + 2 * t4;
        float b0 = 0.f, b1 = 0.f;
        if (epi & 1) { b0 = bias[col]; b1 = bias[col + 1]; }
        #pragma unroll
        for (int mf = 0; mf < 4; mf++) {
            long r1 = m0 + wmI * 64 + mf * 16 + g;
            #pragma unroll
            for (int hh = 0; hh < 2; hh++) {
                long rr = r1 + hh * 8;
                float v0 = acc[mf][nf][hh * 2]     + b0;
                float v1 = acc[mf][nf][hh * 2 + 1] + b1;
                if (epi & 2) { v0 = gelu_f(v0); v1 = gelu_f(v1); }
                if (epi & 4) { v0 += Res[rr * ldc + col]; v1 += Res[rr * ldc + col + 1]; }
                if constexpr (sizeof(CT) == 2) {
                    __half2 hv = __floats2half2_rn(v0, v1);
                    *(__half2*)((__half*)C + rr * ldc + col) = hv;
                } else {
                    if (epi & 8) { v0 = rn_tf32(v0); v1 = rn_tf32(v1); }
                    *(float2*)((float*)C + rr * ldc + col) = make_float2(v0, v1);
                }
            }
        }
    }
}

// ---------------- flash attention ----------------
// grid (SEQ/128, NBATCH*NHEADS), 256 threads (8 warps x 16 Q-rows).
// Q,K fp16 [tok][1024]; V fp32 tf32-rounded [tok][1024]; O fp16 [tok][1024].
#define FK_B   18432    // K buf: 128 x 72 halves (144B)
#define FV_B   36864    // V buf: 128 x 72 floats (288B)
#define FP_OFF (2*FK_B + 2*FV_B)         // 110592
#define FSMEM  (FP_OFF + 128*132*4)      // 178176

__global__ void __launch_bounds__(256) flash_kernel(
    const __half* __restrict__ Q, const __half* __restrict__ Kg,
    const float* __restrict__ Vg, __half* __restrict__ O)
{
    extern __shared__ char sm[];
    const int tid = threadIdx.x;
    const int wid = tid >> 5, lane = tid & 31;
    const int g = lane >> 2, t4 = lane & 3;
    const int wrow = wid * 16;

    const int bh = blockIdx.y;
    const long tok0 = (long)(bh >> 4) * SEQ;
    const int hd0 = (bh & 15) * HEADD;
    const int q0 = blockIdx.x * 128;

    // Q a-frags (scaled by 1/8, exact in fp16)
    const __half* qp = Q + (tok0 + q0) * DMODEL + hd0;
    uint32_t qa[4][4];
    const __half2 qs = __half2half2(__float2half(0.125f));
    #pragma unroll
    for (int ks = 0; ks < 4; ks++) {
        int col = ks * 16 + 2 * t4;
        __half2 a0 = __hmul2(*(const __half2*)(qp + (long)(wrow + g) * DMODEL + col), qs);
        __half2 a1 = __hmul2(*(const __half2*)(qp + (long)(wrow + g + 8) * DMODEL + col), qs);
        __half2 a2 = __hmul2(*(const __half2*)(qp + (long)(wrow + g) * DMODEL + col + 8), qs);
        __half2 a3 = __hmul2(*(const __half2*)(qp + (long)(wrow + g + 8) * DMODEL + col + 8), qs);
        qa[ks][0] = *(uint32_t*)&a0; qa[ks][1] = *(uint32_t*)&a1;
        qa[ks][2] = *(uint32_t*)&a2; qa[ks][3] = *(uint32_t*)&a3;
    }

    float m0 = -1e30f, m1 = -1e30f, l0 = 0.f, l1 = 0.f;
    float oacc[8][4];
    #pragma unroll
    for (int i = 0; i < 8; i++)
        #pragma unroll
        for (int u = 0; u < 4; u++) oacc[i][u] = 0.f;

    auto loadKV = [&](int j) {
        int bb = j & 1;
        char* sK = sm + bb * FK_B;
        char* sV = sm + 2 * FK_B + bb * FV_B;
        const __half* kp = Kg + (tok0 + j * 128) * DMODEL + hd0;
        const float*  vp = Vg + (tok0 + j * 128) * DMODEL + hd0;
        #pragma unroll
        for (int i = 0; i < 4; i++) {            // K: 128 rows x 8 chunks
            int ch = tid + i * 256;
            int row = ch >> 3, c = ch & 7;
            cpasync16(sK + row * 144 + c * 16, kp + (long)row * DMODEL + c * 8);
        }
        #pragma unroll
        for (int i = 0; i < 8; i++) {            // V: 128 rows x 16 chunks
            int ch = tid + i * 256;
            int row = ch >> 4, c = ch & 15;
            cpasync16(sV + row * 288 + c * 16, vp + (long)row * DMODEL + c * 4);
        }
    };

    const int NC = SEQ / 128;   // 16
    loadKV(0); cp_commit();

    for (int j = 0; j < NC; j++) {
        cp_wait<0>();
        __syncthreads();
        if (j + 1 < NC) { loadKV(j + 1); cp_commit(); }

        const __half* sK = (const __half*)(sm + (j & 1) * FK_B);
        const float*  sV = (const float*)(sm + 2 * FK_B + (j & 1) * FV_B);
        float* sP = (float*)(sm + FP_OFF);

        // ---- S = (Q/8) @ K^T, fp32 acc ----
        float sacc[16][4];
        #pragma unroll
        for (int i = 0; i < 16; i++)
            #pragma unroll
            for (int u = 0; u < 4; u++) sacc[i][u] = 0.f;
        #pragma unroll
        for (int ks = 0; ks < 4; ks++) {
            #pragma unroll
            for (int nf = 0; nf < 16; nf++) {
                int n = nf * 8 + g;
                uint32_t b0 = *(const uint32_t*)(sK + n * 72 + ks * 16 + 2 * t4);
                uint32_t b1 = *(const uint32_t*)(sK + n * 72 + ks * 16 + 2 * t4 + 8);
                mma_f16(sacc[nf], qa[ks], b0, b1);
            }
        }

        // ---- online softmax ----
        float mx0 = -1e30f, mx1 = -1e30f;
        #pragma unroll
        for (int nf = 0; nf < 16; nf++) {
            mx0 = fmaxf(mx0, fmaxf(sacc[nf][0], sacc[nf][1]));
            mx1 = fmaxf(mx1, fmaxf(sacc[nf][2], sacc[nf][3]));
        }
        mx0 = fmaxf(mx0, __shfl_xor_sync(0xffffffffu, mx0, 1));
        mx0 = fmaxf(mx0, __shfl_xor_sync(0xffffffffu, mx0, 2));
        mx1 = fmaxf(mx1, __shfl_xor_sync(0xffffffffu, mx1, 1));
        mx1 = fmaxf(mx1, __shfl_xor_sync(0xffffffffu, mx1, 2));
        float nm0 = fmaxf(m0, mx0), nm1 = fmaxf(m1, mx1);
        float cr0 = __expf(m0 - nm0), cr1 = __expf(m1 - nm1);
        m0 = nm0; m1 = nm1;

        float rs0 = 0.f, rs1 = 0.f;
        #pragma unroll
        for (int nf = 0; nf < 16; nf++) {
            float p00 = __expf(sacc[nf][0] - m0);
            float p01 = __expf(sacc[nf][1] - m0);
            float p10 = __expf(sacc[nf][2] - m1);
            float p11 = __expf(sacc[nf][3] - m1);
            rs0 += p00 + p01; rs1 += p10 + p11;
            int cc = nf * 8 + 2 * t4;
            *(float2*)(sP + (wrow + g) * 132 + cc)     = make_float2(rn_tf32(p00), rn_tf32(p01));
            *(float2*)(sP + (wrow + g + 8) * 132 + cc) = make_float2(rn_tf32(p10), rn_tf32(p11));
        }
        rs0 += __shfl_xor_sync(0xffffffffu, rs0, 1);
        rs0 += __shfl_xor_sync(0xffffffffu, rs0, 2);
        rs1 += __shfl_xor_sync(0xffffffffu, rs1, 1);
        rs1 += __shfl_xor_sync(0xffffffffu, rs1, 2);
        l0 = l0 * cr0 + rs0;
        l1 = l1 * cr1 + rs1;
        #pragma unroll
        for (int nf = 0; nf < 8; nf++) {
            oacc[nf][0] *= cr0; oacc[nf][1] *= cr0;
            oacc[nf][2] *= cr1; oacc[nf][3] *= cr1;
        }
        __syncwarp();

        // ---- O += P @ V (tf32) ----
        #pragma unroll
        for (int kc = 0; kc < 16; kc++) {
            uint32_t a[4];
            a[0] = __float_as_uint(sP[(wrow + g) * 132 + kc * 8 + t4]);
            a[1] = __float_as_uint(sP[(wrow + g + 8) * 132 + kc * 8 + t4]);
            a[2] = __float_as_uint(sP[(wrow + g) * 132 + kc * 8 + t4 + 4]);
            a[3] = __float_as_uint(sP[(wrow + g + 8) * 132 + kc * 8 + t4 + 4]);
            #pragma unroll
            for (int nf = 0; nf < 8; nf++) {
                uint32_t b0 = __float_as_uint(sV[(kc * 8 + t4) * 72 + nf * 8 + g]);
                uint32_t b1 = __float_as_uint(sV[(kc * 8 + t4 + 4) * 72 + nf * 8 + g]);
                mma_tf32(oacc[nf], a, b0, b1);
            }
        }
    }

    // ---- write O ----
    float i0 = 1.0f / l0, i1 = 1.0f / l1;
    __half* op = O + (tok0 + q0) * DMODEL + hd0;
    #pragma unroll
    for (int nf = 0; nf < 8; nf++) {
        int col = nf * 8 + 2 * t4;
        __half2 h0 = __floats2half2_rn(oacc[nf][0] * i0, oacc[nf][1] * i0);
        __half2 h1 = __floats2half2_rn(oacc[nf][2] * i1, oacc[nf][3] * i1);
        *(__half2*)(op + (long)(wrow + g) * DMODEL + col) = h0;
        *(__half2*)(op + (long)(wrow + g + 8) * DMODEL + col) = h1;
    }
}

// ---------------- launch ----------------
extern "C" void kernel_launch(void* const* d_in, const int* in_sizes, int n_in,
                              void* d_out, int out_size)
{
    const float* x   = (const float*)d_in[0];
    const float* Wq  = (const float*)d_in[1];
    const float* bq  = (const float*)d_in[2];
    const float* Wk  = (const float*)d_in[3];
    const float* bk  = (const float*)d_in[4];
    const float* Wv  = (const float*)d_in[5];
    const float* bv  = (const float*)d_in[6];
    const float* Wp  = (const float*)d_in[7];
    const float* bp  = (const float*)d_in[8];
    const float* W1  = (const float*)d_in[9];
    const float* b1  = (const float*)d_in[10];
    const float* W2  = (const float*)d_in[11];
    const float* b2  = (const float*)d_in[12];
    const float* g1  = (const float*)d_in[13];
    const float* be1 = (const float*)d_in[14];
    const float* g2  = (const float*)d_in[15];
    const float* be2 = (const float*)d_in[16];
    float* out = (float*)d_out;

    __half *h, *q, *k, *att, *h2, *ff, *wq, *wk, *wv, *wp, *w1, *w2;
    float *v, *x1;
    cudaGetSymbolAddress((void**)&h,   g_h);
    cudaGetSymbolAddress((void**)&q,   g_q);
    cudaGetSymbolAddress((void**)&k,   g_k);
    cudaGetSymbolAddress((void**)&v,   g_v);
    cudaGetSymbolAddress((void**)&att, g_att);
    cudaGetSymbolAddress((void**)&x1,  g_x1);
    cudaGetSymbolAddress((void**)&h2,  g_h2);
    cudaGetSymbolAddress((void**)&ff,  g_ff);
    cudaGetSymbolAddress((void**)&wq,  g_wq);
    cudaGetSymbolAddress((void**)&wk,  g_wk);
    cudaGetSymbolAddress((void**)&wv,  g_wv);
    cudaGetSymbolAddress((void**)&wp,  g_wp);
    cudaGetSymbolAddress((void**)&w1,  g_w1);
    cudaGetSymbolAddress((void**)&w2,  g_w2);

    const int smemG = 3 * 2 * 128 * PAH * 2;   // 61440
    static bool attr_done = false;
    if (!attr_done) {
        cudaFuncSetAttribute(hgemm<__half>,
            cudaFuncAttributeMaxDynamicSharedMemorySize, smemG);
        cudaFuncSetAttribute(hgemm<float>,
            cudaFuncAttributeMaxDynamicSharedMemorySize, smemG);
        cudaFuncSetAttribute(flash_kernel,
            cudaFuncAttributeMaxDynamicSharedMemorySize, FSMEM);
        attr_done = true;
    }

    dim3 tb(32, 8);
    // 0) weight transposes -> fp16 K-major
    wtrans<<<dim3(DMODEL / 32, DMODEL / 32), tb>>>(Wq, wq, DMODEL, DMODEL);
    wtrans<<<dim3(DMODEL / 32, DMODEL / 32), tb>>>(Wk, wk, DMODEL, DMODEL);
    wtrans<<<dim3(DMODEL / 32, DMODEL / 32), tb>>>(Wv, wv, DMODEL, DMODEL);
    wtrans<<<dim3(DMODEL / 32, DMODEL / 32), tb>>>(Wp, wp, DMODEL, DMODEL);
    wtrans<<<dim3(DFF / 32, DMODEL / 32), tb>>>(W1, w1, DMODEL, DFF);
    wtrans<<<dim3(DMODEL / 32, DFF / 32), tb>>>(W2, w2, DFF, DMODEL);

    // 1) LN1 -> h (fp16)
    ln_kernel<<<NTOK, 256>>>(x, g1, be1, h);

    // 2) Q, K (fp16 out), V (fp32 tf32-rounded out)
    dim3 gP(DMODEL / 128, NTOK / 128);
    hgemm<__half><<<gP, 256, smemG>>>(h, wq, bq, nullptr, q, DMODEL, DMODEL, DMODEL, DMODEL, 1);
    hgemm<__half><<<gP, 256, smemG>>>(h, wk, bk, nullptr, k, DMODEL, DMODEL, DMODEL, DMODEL, 1);
    hgemm<float ><<<gP, 256, smemG>>>(h, wv, bv, nullptr, v, DMODEL, DMODEL, DMODEL, DMODEL, 1 | 8);

    // 3-5) fused flash attention -> att (fp16)
    flash_kernel<<<dim3(SEQ / 128, NBATCH * NHEADS), 256, FSMEM>>>(q, k, v, att);

    // 6) x1 = x + att @ Wp + bp (fp32)
    hgemm<float><<<gP, 256, smemG>>>(att, wp, bp, x, x1, DMODEL, DMODEL, DMODEL, DMODEL, 1 | 4);

    // 7) LN2 -> h2 (fp16)
    ln_kernel<<<NTOK, 256>>>(x1, g2, be2, h2);

    // 8) ff = gelu(h2 @ W1 + b1) (fp16)
    dim3 gF1(DFF / 128, NTOK / 128);
    hgemm<__half><<<gF1, 256, smemG>>>(h2, w1, b1, nullptr, ff, DMODEL, DMODEL, DMODEL, DFF, 1 | 2);

    // 9) out = x1 + ff @ W2 + b2 (fp32)
    dim3 gF2(DMODEL / 128, NTOK / 128);
    hgemm<float><<<gF2, 256, smemG>>>(ff, w2, b2, x1, out, DFF, DFF, DFF, DMODEL, 1 | 4);
}

// round 7
// speedup vs baseline: 4.3774x; 1.2708x over previous
#include <cuda_runtime.h>
#include <cuda_fp16.h>
#include <math.h>
#include <cstdint>
#include <cstddef>

#define DMODEL 1024
#define DFF    4096
#define NHEADS 16
#define HEADD  64
#define SEQ    2048
#define NBATCH 2
#define NTOK   (NBATCH * SEQ)   // 4096
#define D3     (3 * DMODEL)     // 3072

// ---------------- scratch ----------------
__device__ __half g_h   [(size_t)NTOK * DMODEL];
__device__ __half g_qkv [(size_t)NTOK * D3];
__device__ __half g_att [(size_t)NTOK * DMODEL];
__device__ float  g_x1  [(size_t)NTOK * DMODEL];
__device__ __half g_h2  [(size_t)NTOK * DMODEL];
__device__ __half g_ff  [(size_t)NTOK * DFF];
__device__ __half g_wqkv[(size_t)D3 * DMODEL];    // K-major [3072][1024]
__device__ float  g_bqkv[(size_t)D3];
__device__ __half g_wp  [(size_t)DMODEL * DMODEL];
__device__ __half g_w1  [(size_t)DFF * DMODEL];
__device__ __half g_w2  [(size_t)DMODEL * DFF];

// ---------------- helpers ----------------
__device__ __forceinline__ float warpSum(float v) {
    #pragma unroll
    for (int o = 16; o > 0; o >>= 1) v += __shfl_xor_sync(0xffffffffu, v, o);
    return v;
}
__device__ __forceinline__ float gelu_f(float x) {
    const float c = 0.7978845608028654f;
    float u = c * (x + 0.044715f * x * x * x);
    float e = __expf(2.0f * fminf(u, 12.0f));
    return x * e / (e + 1.0f);
}
__device__ __forceinline__ void cpasync16(void* s, const void* g) {
    unsigned int sa = (unsigned int)__cvta_generic_to_shared(s);
    asm volatile("cp.async.cg.shared.global [%0], [%1], 16;\n" :: "r"(sa), "l"(g));
}
__device__ __forceinline__ void cp_commit() {
    asm volatile("cp.async.commit_group;\n");
}
template <int N>
__device__ __forceinline__ void cp_wait() {
    asm volatile("cp.async.wait_group %0;\n" :: "n"(N));
}
__device__ __forceinline__ void mma_f16(float* c, const uint32_t* a, uint32_t b0, uint32_t b1) {
    asm volatile(
        "mma.sync.aligned.m16n8k16.row.col.f32.f16.f16.f32 "
        "{%0,%1,%2,%3}, {%4,%5,%6,%7}, {%8,%9}, {%0,%1,%2,%3};\n"
        : "+f"(c[0]), "+f"(c[1]), "+f"(c[2]), "+f"(c[3])
        : "r"(a[0]), "r"(a[1]), "r"(a[2]), "r"(a[3]), "r"(b0), "r"(b1));
}
__device__ __forceinline__ void ldmx4t(uint32_t* r, unsigned int addr) {
    asm volatile(
        "ldmatrix.sync.aligned.m8n8.x4.trans.shared.b16 {%0,%1,%2,%3}, [%4];"
        : "=r"(r[0]), "=r"(r[1]), "=r"(r[2]), "=r"(r[3]) : "r"(addr));
}

// ---------------- weight transpose fp32[K][N] -> fp16[N][K] ----------------
__global__ void __launch_bounds__(256) wtrans(
    const float* __restrict__ in, __half* __restrict__ out, int K, int N)
{
    __shared__ float t[32][33];
    int n0 = blockIdx.x * 32, k0 = blockIdx.y * 32;
    int tx = threadIdx.x, ty = threadIdx.y;
    #pragma unroll
    for (int i = ty; i < 32; i += 8)
        t[i][tx] = in[(long)(k0 + i) * N + n0 + tx];
    __syncthreads();
    #pragma unroll
    for (int i = ty; i < 32; i += 8)
        out[(long)(n0 + i) * K + k0 + tx] = __float2half_rn(t[tx][i]);
}

__global__ void __launch_bounds__(256) bcat(
    const float* __restrict__ a, const float* __restrict__ b,
    const float* __restrict__ c, float* __restrict__ o)
{
    int i = blockIdx.x * 256 + threadIdx.x;     // 0..3071
    float v = (i < 1024) ? a[i] : (i < 2048) ? b[i - 1024] : c[i - 2048];
    o[i] = v;
}

// ---------------- LayerNorm: fp32 in -> fp16 out ----------------
__global__ void __launch_bounds__(256) ln_kernel(
    const float* __restrict__ X, const float* __restrict__ g,
    const float* __restrict__ b, __half* __restrict__ Y)
{
    long row = blockIdx.x;
    int tid = threadIdx.x;
    const float* x = X + row * DMODEL;
    float4 xv = *(const float4*)(x + tid * 4);
    float s  = xv.x + xv.y + xv.z + xv.w;
    float s2 = xv.x * xv.x + xv.y * xv.y + xv.z * xv.z + xv.w * xv.w;
    s = warpSum(s); s2 = warpSum(s2);
    __shared__ float sh[2][8];
    int w = tid >> 5, l = tid & 31;
    if (l == 0) { sh[0][w] = s; sh[1][w] = s2; }
    __syncthreads();
    if (w == 0) {
        float a = (l < 8) ? sh[0][l] : 0.f;
        float c = (l < 8) ? sh[1][l] : 0.f;
        a = warpSum(a); c = warpSum(c);
        if (l == 0) { sh[0][0] = a; sh[1][0] = c; }
    }
    __syncthreads();
    float mean = sh[0][0] * (1.0f / DMODEL);
    float var  = sh[1][0] * (1.0f / DMODEL) - mean * mean;
    float rstd = rsqrtf(var + 1e-5f);
    float4 gv = *(const float4*)(g + tid * 4);
    float4 bv = *(const float4*)(b + tid * 4);
    __half2 h0 = __floats2half2_rn((xv.x - mean) * rstd * gv.x + bv.x,
                                   (xv.y - mean) * rstd * gv.y + bv.y);
    __half2 h1 = __floats2half2_rn((xv.z - mean) * rstd * gv.z + bv.z,
                                   (xv.w - mean) * rstd * gv.w + bv.w);
    uint2 u;
    u.x = *(uint32_t*)&h0; u.y = *(uint32_t*)&h1;
    *(uint2*)(Y + row * DMODEL + tid * 4) = u;
}

// ---------------- fp16 GEMM: C[M,N] = A[M,K]@Bt[N,K]^T + epi ----------------
// epi: 1=+bias, 2=gelu, 4=+Res(fp32, ldc)
#define PAH 40     // smem pitch in halves (80B)

template <typename CT>
__global__ void __launch_bounds__(256) hgemm(
    const __half* __restrict__ A, const __half* __restrict__ B,
    const float* __restrict__ bias, const float* __restrict__ Res,
    CT* __restrict__ C, int K, int lda, int ldb, int ldc, int epi)
{
    constexpr int STGB = 2 * 128 * PAH * 2;   // 20480 B/stage
    extern __shared__ char smem[];

    const int m0 = blockIdx.y * 128;
    const int n0 = blockIdx.x * 128;
    const int tid = threadIdx.x;
    const int wid = tid >> 5, lane = tid & 31;
    const int wmI = wid >> 2, wnI = wid & 3;
    const int g = lane >> 2, t4 = lane & 3;

    float acc[4][4][4];
    #pragma unroll
    for (int i = 0; i < 4; i++)
        #pragma unroll
        for (int j = 0; j < 4; j++)
            #pragma unroll
            for (int u = 0; u < 4; u++) acc[i][j][u] = 0.f;

    auto load_stage = [&](int s, int k0) {
        char* st = smem + s * STGB;
        #pragma unroll
        for (int i = 0; i < 2; i++) {
            int ch = tid + i * 256;
            int row = ch >> 2, c = ch & 3;
            cpasync16(st + row * 80 + c * 16,
                      A + (long)(m0 + row) * lda + k0 + c * 8);
        }
        char* stB = st + 128 * 80;
        #pragma unroll
        for (int i = 0; i < 2; i++) {
            int ch = tid + i * 256;
            int row = ch >> 2, c = ch & 3;
            cpasync16(stB + row * 80 + c * 16,
                      B + (long)(n0 + row) * ldb + k0 + c * 8);
        }
    };

    const int kt = K / 32;
    load_stage(0, 0);  cp_commit();
    load_stage(1, 32); cp_commit();

    for (int it = 0; it < kt; it++) {
        cp_wait<1>();
        __syncthreads();
        if (it + 2 < kt) load_stage((it + 2) % 3, (it + 2) * 32);
        cp_commit();

        const __half* sA = (const __half*)(smem + (it % 3) * STGB);
        const __half* sB = sA + 128 * PAH;

        #pragma unroll
        for (int kk = 0; kk < 32; kk += 16) {
            uint32_t af[4][4], bf[4][2];
            #pragma unroll
            for (int mf = 0; mf < 4; mf++) {
                int r = wmI * 64 + mf * 16 + g;
                af[mf][0] = *(const uint32_t*)(sA + r * PAH + kk + 2 * t4);
                af[mf][1] = *(const uint32_t*)(sA + (r + 8) * PAH + kk + 2 * t4);
                af[mf][2] = *(const uint32_t*)(sA + r * PAH + kk + 2 * t4 + 8);
                af[mf][3] = *(const uint32_t*)(sA + (r + 8) * PAH + kk + 2 * t4 + 8);
            }
            #pragma unroll
            for (int nf = 0; nf < 4; nf++) {
                int n = wnI * 32 + nf * 8 + g;
                bf[nf][0] = *(const uint32_t*)(sB + n * PAH + kk + 2 * t4);
                bf[nf][1] = *(const uint32_t*)(sB + n * PAH + kk + 2 * t4 + 8);
            }
            #pragma unroll
            for (int mf = 0; mf < 4; mf++)
                #pragma unroll
                for (int nf = 0; nf < 4; nf++)
                    mma_f16(acc[mf][nf], af[mf], bf[nf][0], bf[nf][1]);
        }
        __syncthreads();
    }

    #pragma unroll
    for (int nf = 0; nf < 4; nf++) {
        int col = n0 + wnI * 32 + nf * 8 + 2 * t4;
        float b0 = 0.f, b1 = 0.f;
        if (epi & 1) { b0 = bias[col]; b1 = bias[col + 1]; }
        #pragma unroll
        for (int mf = 0; mf < 4; mf++) {
            long r1 = m0 + wmI * 64 + mf * 16 + g;
            #pragma unroll
            for (int hh = 0; hh < 2; hh++) {
                long rr = r1 + hh * 8;
                float v0 = acc[mf][nf][hh * 2]     + b0;
                float v1 = acc[mf][nf][hh * 2 + 1] + b1;
                if (epi & 2) { v0 = gelu_f(v0); v1 = gelu_f(v1); }
                if (epi & 4) { v0 += Res[rr * ldc + col]; v1 += Res[rr * ldc + col + 1]; }
                if constexpr (sizeof(CT) == 2) {
                    __half2 hv = __floats2half2_rn(v0, v1);
                    *(__half2*)((__half*)C + rr * ldc + col) = hv;
                } else {
                    *(float2*)((float*)C + rr * ldc + col) = make_float2(v0, v1);
                }
            }
        }
    }
}

// ---------------- flash attention (all-fp16 mma, register P) ----------------
// grid (SEQ/128, NBATCH*NHEADS), 256 threads (8 warps x 16 Q-rows).
// QKV packed fp16 [tok][3072]; O fp16 [tok][1024].
#define FKB 18432            // 128 x 72 halves (144B pitch)
#define FSMEM (4 * FKB)      // 73728

__global__ void __launch_bounds__(256) flash_kernel(
    const __half* __restrict__ QKV, __half* __restrict__ O)
{
    extern __shared__ char sm[];
    const int tid = threadIdx.x;
    const int wid = tid >> 5, lane = tid & 31;
    const int g = lane >> 2, t4 = lane & 3;
    const int wrow = wid * 16;

    const int bh = blockIdx.y;
    const long tok0 = (long)(bh >> 4) * SEQ;
    const int hd0 = (bh & 15) * HEADD;
    const int q0 = blockIdx.x * 128;

    // Q a-frags (scaled by 1/8, exact in fp16)
    const __half* qp = QKV + (tok0 + q0) * D3 + hd0;
    uint32_t qa[4][4];
    const __half2 qs = __half2half2(__float2half(0.125f));
    #pragma unroll
    for (int ks = 0; ks < 4; ks++) {
        int col = ks * 16 + 2 * t4;
        __half2 a0 = __hmul2(*(const __half2*)(qp + (long)(wrow + g) * D3 + col), qs);
        __half2 a1 = __hmul2(*(const __half2*)(qp + (long)(wrow + g + 8) * D3 + col), qs);
        __half2 a2 = __hmul2(*(const __half2*)(qp + (long)(wrow + g) * D3 + col + 8), qs);
        __half2 a3 = __hmul2(*(const __half2*)(qp + (long)(wrow + g + 8) * D3 + col + 8), qs);
        qa[ks][0] = *(uint32_t*)&a0; qa[ks][1] = *(uint32_t*)&a1;
        qa[ks][2] = *(uint32_t*)&a2; qa[ks][3] = *(uint32_t*)&a3;
    }

    float m0 = -1e30f, m1 = -1e30f, l0 = 0.f, l1 = 0.f;
    float oacc[8][4];
    #pragma unroll
    for (int i = 0; i < 8; i++)
        #pragma unroll
        for (int u = 0; u < 4; u++) oacc[i][u] = 0.f;

    auto loadKV = [&](int j) {
        int bb = j & 1;
        char* sK = sm + bb * FKB;
        char* sV = sm + (2 + bb) * FKB;
        const __half* kp = QKV + (tok0 + j * 128) * D3 + DMODEL + hd0;
        const __half* vp = QKV + (tok0 + j * 128) * D3 + 2 * DMODEL + hd0;
        #pragma unroll
        for (int i = 0; i < 4; i++) {
            int ch = tid + i * 256;
            int row = ch >> 3, c = ch & 7;
            cpasync16(sK + row * 144 + c * 16, kp + (long)row * D3 + c * 8);
        }
        #pragma unroll
        for (int i = 0; i < 4; i++) {
            int ch = tid + i * 256;
            int row = ch >> 3, c = ch & 7;
            cpasync16(sV + row * 144 + c * 16, vp + (long)row * D3 + c * 8);
        }
    };

    // ldmatrix V address (per PV k-chunk/np group): lane-dependent base
    const int ltile = lane >> 3;                  // 0..3
    const int lrow  = lane & 7;
    const int vko   = (ltile & 1) * 8 + lrow;     // k row within 16-chunk
    const int vno   = (ltile >> 1) * 8;           // n col offset within 16-group

    const int NC = SEQ / 128;   // 16
    loadKV(0); cp_commit();

    for (int j = 0; j < NC; j++) {
        cp_wait<0>();
        __syncthreads();
        if (j + 1 < NC) { loadKV(j + 1); cp_commit(); }

        const __half* sK = (const __half*)(sm + (j & 1) * FKB);
        unsigned int sVb;
        {
            const __half* sV = (const __half*)(sm + (2 + (j & 1)) * FKB);
            sVb = (unsigned int)__cvta_generic_to_shared(sV);
        }

        // ---- S = (Q/8) @ K^T ----
        float sacc[16][4];
        #pragma unroll
        for (int i = 0; i < 16; i++)
            #pragma unroll
            for (int u = 0; u < 4; u++) sacc[i][u] = 0.f;
        #pragma unroll
        for (int ks = 0; ks < 4; ks++) {
            #pragma unroll
            for (int nf = 0; nf < 16; nf++) {
                int n = nf * 8 + g;
                uint32_t b0 = *(const uint32_t*)(sK + n * 72 + ks * 16 + 2 * t4);
                uint32_t b1 = *(const uint32_t*)(sK + n * 72 + ks * 16 + 2 * t4 + 8);
                mma_f16(sacc[nf], qa[ks], b0, b1);
            }
        }

        // ---- online softmax (in registers) ----
        float mx0 = -1e30f, mx1 = -1e30f;
        #pragma unroll
        for (int nf = 0; nf < 16; nf++) {
            mx0 = fmaxf(mx0, fmaxf(sacc[nf][0], sacc[nf][1]));
            mx1 = fmaxf(mx1, fmaxf(sacc[nf][2], sacc[nf][3]));
        }
        mx0 = fmaxf(mx0, __shfl_xor_sync(0xffffffffu, mx0, 1));
        mx0 = fmaxf(mx0, __shfl_xor_sync(0xffffffffu, mx0, 2));
        mx1 = fmaxf(mx1, __shfl_xor_sync(0xffffffffu, mx1, 1));
        mx1 = fmaxf(mx1, __shfl_xor_sync(0xffffffffu, mx1, 2));
        float nm0 = fmaxf(m0, mx0), nm1 = fmaxf(m1, mx1);
        float cr0 = __expf(m0 - nm0), cr1 = __expf(m1 - nm1);
        m0 = nm0; m1 = nm1;

        float rs0 = 0.f, rs1 = 0.f;
        #pragma unroll
        for (int nf = 0; nf < 16; nf++) {
            sacc[nf][0] = __expf(sacc[nf][0] - m0);
            sacc[nf][1] = __expf(sacc[nf][1] - m0);
            sacc[nf][2] = __expf(sacc[nf][2] - m1);
            sacc[nf][3] = __expf(sacc[nf][3] - m1);
            rs0 += sacc[nf][0] + sacc[nf][1];
            rs1 += sacc[nf][2] + sacc[nf][3];
        }
        rs0 += __shfl_xor_sync(0xffffffffu, rs0, 1);
        rs0 += __shfl_xor_sync(0xffffffffu, rs0, 2);
        rs1 += __shfl_xor_sync(0xffffffffu, rs1, 1);
        rs1 += __shfl_xor_sync(0xffffffffu, rs1, 2);
        l0 = l0 * cr0 + rs0;
        l1 = l1 * cr1 + rs1;
        #pragma unroll
        for (int nf = 0; nf < 8; nf++) {
            oacc[nf][0] *= cr0; oacc[nf][1] *= cr0;
            oacc[nf][2] *= cr1; oacc[nf][3] *= cr1;
        }

        // ---- O += P @ V, all fp16, P direct from registers ----
        #pragma unroll
        for (int kc = 0; kc < 8; kc++) {
            uint32_t a[4];
            __half2 p0 = __floats2half2_rn(sacc[2 * kc][0],     sacc[2 * kc][1]);
            __half2 p1 = __floats2half2_rn(sacc[2 * kc][2],     sacc[2 * kc][3]);
            __half2 p2 = __floats2half2_rn(sacc[2 * kc + 1][0], sacc[2 * kc + 1][1]);
            __half2 p3 = __floats2half2_rn(sacc[2 * kc + 1][2], sacc[2 * kc + 1][3]);
            a[0] = *(uint32_t*)&p0; a[1] = *(uint32_t*)&p1;
            a[2] = *(uint32_t*)&p2; a[3] = *(uint32_t*)&p3;
            #pragma unroll
            for (int np = 0; np < 4; np++) {
                uint32_t vr[4];
                unsigned int addr = sVb +
                    ((kc * 16 + vko) * 72 + np * 16 + vno) * 2;
                ldmx4t(vr, addr);
                mma_f16(oacc[2 * np],     a, vr[0], vr[1]);
                mma_f16(oacc[2 * np + 1], a, vr[2], vr[3]);
            }
        }
    }

    // ---- write O ----
    float i0 = 1.0f / l0, i1 = 1.0f / l1;
    __half* op = O + (tok0 + q0) * DMODEL + hd0;
    #pragma unroll
    for (int nf = 0; nf < 8; nf++) {
        int col = nf * 8 + 2 * t4;
        __half2 h0 = __floats2half2_rn(oacc[nf][0] * i0, oacc[nf][1] * i0);
        __half2 h1 = __floats2half2_rn(oacc[nf][2] * i1, oacc[nf][3] * i1);
        *(__half2*)(op + (long)(wrow + g) * DMODEL + col) = h0;
        *(__half2*)(op + (long)(wrow + g + 8) * DMODEL + col) = h1;
    }
}

// ---------------- launch ----------------
extern "C" void kernel_launch(void* const* d_in, const int* in_sizes, int n_in,
                              void* d_out, int out_size)
{
    const float* x   = (const float*)d_in[0];
    const float* Wq  = (const float*)d_in[1];
    const float* bq  = (const float*)d_in[2];
    const float* Wk  = (const float*)d_in[3];
    const float* bk  = (const float*)d_in[4];
    const float* Wv  = (const float*)d_in[5];
    const float* bv  = (const float*)d_in[6];
    const float* Wp  = (const float*)d_in[7];
    const float* bp  = (const float*)d_in[8];
    const float* W1  = (const float*)d_in[9];
    const float* b1  = (const float*)d_in[10];
    const float* W2  = (const float*)d_in[11];
    const float* b2  = (const float*)d_in[12];
    const float* g1  = (const float*)d_in[13];
    const float* be1 = (const float*)d_in[14];
    const float* g2  = (const float*)d_in[15];
    const float* be2 = (const float*)d_in[16];
    float* out = (float*)d_out;

    __half *h, *qkv, *att, *h2, *ff, *wqkv, *wp, *w1, *w2;
    float *x1, *bqkv;
    cudaGetSymbolAddress((void**)&h,    g_h);
    cudaGetSymbolAddress((void**)&qkv,  g_qkv);
    cudaGetSymbolAddress((void**)&att,  g_att);
    cudaGetSymbolAddress((void**)&x1,   g_x1);
    cudaGetSymbolAddress((void**)&h2,   g_h2);
    cudaGetSymbolAddress((void**)&ff,   g_ff);
    cudaGetSymbolAddress((void**)&wqkv, g_wqkv);
    cudaGetSymbolAddress((void**)&bqkv, g_bqkv);
    cudaGetSymbolAddress((void**)&wp,   g_wp);
    cudaGetSymbolAddress((void**)&w1,   g_w1);
    cudaGetSymbolAddress((void**)&w2,   g_w2);

    const int smemG = 3 * 2 * 128 * PAH * 2;   // 61440
    static bool attr_done = false;
    if (!attr_done) {
        cudaFuncSetAttribute(hgemm<__half>,
            cudaFuncAttributeMaxDynamicSharedMemorySize, smemG);
        cudaFuncSetAttribute(hgemm<float>,
            cudaFuncAttributeMaxDynamicSharedMemorySize, smemG);
        cudaFuncSetAttribute(flash_kernel,
            cudaFuncAttributeMaxDynamicSharedMemorySize, FSMEM);
        attr_done = true;
    }

    dim3 tb(32, 8);
    // 0) weights -> fp16 K-major; QKV weights concatenated
    wtrans<<<dim3(DMODEL / 32, DMODEL / 32), tb>>>(Wq, wqkv, DMODEL, DMODEL);
    wtrans<<<dim3(DMODEL / 32, DMODEL / 32), tb>>>(Wk, wqkv + (size_t)DMODEL * DMODEL, DMODEL, DMODEL);
    wtrans<<<dim3(DMODEL / 32, DMODEL / 32), tb>>>(Wv, wqkv + (size_t)2 * DMODEL * DMODEL, DMODEL, DMODEL);
    bcat<<<12, 256>>>(bq, bk, bv, bqkv);
    wtrans<<<dim3(DMODEL / 32, DMODEL / 32), tb>>>(Wp, wp, DMODEL, DMODEL);
    wtrans<<<dim3(DFF / 32, DMODEL / 32), tb>>>(W1, w1, DMODEL, DFF);
    wtrans<<<dim3(DMODEL / 32, DFF / 32), tb>>>(W2, w2, DFF, DMODEL);

    // 1) LN1 -> h (fp16)
    ln_kernel<<<NTOK, 256>>>(x, g1, be1, h);

    // 2) fused QKV projection -> qkv (fp16, [tok][3072])
    dim3 gQKV(D3 / 128, NTOK / 128);
    hgemm<__half><<<gQKV, 256, smemG>>>(h, wqkv, bqkv, nullptr, qkv,
                                        DMODEL, DMODEL, DMODEL, D3, 1);

    // 3) fused flash attention -> att (fp16)
    flash_kernel<<<dim3(SEQ / 128, NBATCH * NHEADS), 256, FSMEM>>>(qkv, att);

    // 4) x1 = x + att @ Wp + bp (fp32)
    dim3 gP(DMODEL / 128, NTOK / 128);
    hgemm<float><<<gP, 256, smemG>>>(att, wp, bp, x, x1, DMODEL, DMODEL, DMODEL, DMODEL, 1 | 4);

    // 5) LN2 -> h2 (fp16)
    ln_kernel<<<NTOK, 256>>>(x1, g2, be2, h2);

    // 6) ff = gelu(h2 @ W1 + b1) (fp16)
    dim3 gF1(DFF / 128, NTOK / 128);
    hgemm<__half><<<gF1, 256, smemG>>>(h2, w1, b1, nullptr, ff, DMODEL, DMODEL, DMODEL, DFF, 1 | 2);

    // 7) out = x1 + ff @ W2 + b2 (fp32)
    dim3 gF2(DMODEL / 128, NTOK / 128);
    hgemm<float><<<gF2, 256, smemG>>>(ff, w2, b2, x1, out, DFF, DFF, DFF, DMODEL, 1 | 4);
}

// round 8
// speedup vs baseline: 4.9096x; 1.1216x over previous
#include <cuda_runtime.h>
#include <cuda_fp16.h>
#include <math.h>
#include <cstdint>
#include <cstddef>

#define DMODEL 1024
#define DFF    4096
#define NHEADS 16
#define HEADD  64
#define SEQ    2048
#define NBATCH 2
#define NTOK   (NBATCH * SEQ)   // 4096
#define D3     (3 * DMODEL)     // 3072

// ---------------- scratch ----------------
__device__ __half g_h   [(size_t)NTOK * DMODEL];
__device__ __half g_qkv [(size_t)NTOK * D3];
__device__ __half g_att [(size_t)NTOK * DMODEL];
__device__ float  g_x1  [(size_t)NTOK * DMODEL];
__device__ __half g_h2  [(size_t)NTOK * DMODEL];
__device__ __half g_ff  [(size_t)NTOK * DFF];
__device__ __half g_wqkv[(size_t)D3 * DMODEL];    // K-major [3072][1024]
__device__ float  g_bqkv[(size_t)D3];
__device__ __half g_wp  [(size_t)DMODEL * DMODEL];
__device__ __half g_w1  [(size_t)DFF * DMODEL];
__device__ __half g_w2  [(size_t)DMODEL * DFF];

// ---------------- helpers ----------------
__device__ __forceinline__ float warpSum(float v) {
    #pragma unroll
    for (int o = 16; o > 0; o >>= 1) v += __shfl_xor_sync(0xffffffffu, v, o);
    return v;
}
__device__ __forceinline__ float gelu_f(float x) {
    const float c = 0.7978845608028654f;
    float u = c * (x + 0.044715f * x * x * x);
    float e = __expf(2.0f * fminf(u, 12.0f));
    return x * e / (e + 1.0f);
}
__device__ __forceinline__ void cpasync16(void* s, const void* g) {
    unsigned int sa = (unsigned int)__cvta_generic_to_shared(s);
    asm volatile("cp.async.cg.shared.global [%0], [%1], 16;\n" :: "r"(sa), "l"(g));
}
__device__ __forceinline__ void cp_commit() {
    asm volatile("cp.async.commit_group;\n");
}
template <int N>
__device__ __forceinline__ void cp_wait() {
    asm volatile("cp.async.wait_group %0;\n" :: "n"(N));
}
__device__ __forceinline__ void mma_f16(float* c, const uint32_t* a, uint32_t b0, uint32_t b1) {
    asm volatile(
        "mma.sync.aligned.m16n8k16.row.col.f32.f16.f16.f32 "
        "{%0,%1,%2,%3}, {%4,%5,%6,%7}, {%8,%9}, {%0,%1,%2,%3};\n"
        : "+f"(c[0]), "+f"(c[1]), "+f"(c[2]), "+f"(c[3])
        : "r"(a[0]), "r"(a[1]), "r"(a[2]), "r"(a[3]), "r"(b0), "r"(b1));
}
__device__ __forceinline__ void ldmx4(uint32_t* r, unsigned int addr) {
    asm volatile(
        "ldmatrix.sync.aligned.m8n8.x4.shared.b16 {%0,%1,%2,%3}, [%4];"
        : "=r"(r[0]), "=r"(r[1]), "=r"(r[2]), "=r"(r[3]) : "r"(addr));
}
__device__ __forceinline__ void ldmx4t(uint32_t* r, unsigned int addr) {
    asm volatile(
        "ldmatrix.sync.aligned.m8n8.x4.trans.shared.b16 {%0,%1,%2,%3}, [%4];"
        : "=r"(r[0]), "=r"(r[1]), "=r"(r[2]), "=r"(r[3]) : "r"(addr));
}

// ---------------- weight transpose fp32[K][N] -> fp16[N][K] ----------------
__global__ void __launch_bounds__(256) wtrans(
    const float* __restrict__ in, __half* __restrict__ out, int K, int N)
{
    __shared__ float t[32][33];
    int n0 = blockIdx.x * 32, k0 = blockIdx.y * 32;
    int tx = threadIdx.x, ty = threadIdx.y;
    #pragma unroll
    for (int i = ty; i < 32; i += 8)
        t[i][tx] = in[(long)(k0 + i) * N + n0 + tx];
    __syncthreads();
    #pragma unroll
    for (int i = ty; i < 32; i += 8)
        out[(long)(n0 + i) * K + k0 + tx] = __float2half_rn(t[tx][i]);
}

__global__ void __launch_bounds__(256) bcat(
    const float* __restrict__ a, const float* __restrict__ b,
    const float* __restrict__ c, float* __restrict__ o)
{
    int i = blockIdx.x * 256 + threadIdx.x;
    float v = (i < 1024) ? a[i] : (i < 2048) ? b[i - 1024] : c[i - 2048];
    o[i] = v;
}

// ---------------- LayerNorm: fp32 in -> fp16 out ----------------
__global__ void __launch_bounds__(256) ln_kernel(
    const float* __restrict__ X, const float* __restrict__ g,
    const float* __restrict__ b, __half* __restrict__ Y)
{
    long row = blockIdx.x;
    int tid = threadIdx.x;
    const float* x = X + row * DMODEL;
    float4 xv = *(const float4*)(x + tid * 4);
    float s  = xv.x + xv.y + xv.z + xv.w;
    float s2 = xv.x * xv.x + xv.y * xv.y + xv.z * xv.z + xv.w * xv.w;
    s = warpSum(s); s2 = warpSum(s2);
    __shared__ float sh[2][8];
    int w = tid >> 5, l = tid & 31;
    if (l == 0) { sh[0][w] = s; sh[1][w] = s2; }
    __syncthreads();
    if (w == 0) {
        float a = (l < 8) ? sh[0][l] : 0.f;
        float c = (l < 8) ? sh[1][l] : 0.f;
        a = warpSum(a); c = warpSum(c);
        if (l == 0) { sh[0][0] = a; sh[1][0] = c; }
    }
    __syncthreads();
    float mean = sh[0][0] * (1.0f / DMODEL);
    float var  = sh[1][0] * (1.0f / DMODEL) - mean * mean;
    float rstd = rsqrtf(var + 1e-5f);
    float4 gv = *(const float4*)(g + tid * 4);
    float4 bv = *(const float4*)(b + tid * 4);
    __half2 h0 = __floats2half2_rn((xv.x - mean) * rstd * gv.x + bv.x,
                                   (xv.y - mean) * rstd * gv.y + bv.y);
    __half2 h1 = __floats2half2_rn((xv.z - mean) * rstd * gv.z + bv.z,
                                   (xv.w - mean) * rstd * gv.w + bv.w);
    uint2 u;
    u.x = *(uint32_t*)&h0; u.y = *(uint32_t*)&h1;
    *(uint2*)(Y + row * DMODEL + tid * 4) = u;
}

// ---------------- fp16 GEMM (ldmatrix inner loop) ----------------
// C[M,N] = A[M,K]@Bt[N,K]^T + epi.  epi: 1=+bias, 2=gelu, 4=+Res(fp32)
#define PAH 40     // smem pitch in halves (80B, conflict-free for ldmatrix)

template <typename CT>
__global__ void __launch_bounds__(256) hgemm(
    const __half* __restrict__ A, const __half* __restrict__ B,
    const float* __restrict__ bias, const float* __restrict__ Res,
    CT* __restrict__ C, int K, int lda, int ldb, int ldc, int epi)
{
    constexpr int STGB = 2 * 128 * PAH * 2;   // 20480 B/stage
    extern __shared__ char smem[];

    const int m0 = blockIdx.y * 128;
    const int n0 = blockIdx.x * 128;
    const int tid = threadIdx.x;
    const int wid = tid >> 5, lane = tid & 31;
    const int wmI = wid >> 2, wnI = wid & 3;
    const int g = lane >> 2, t4 = lane & 3;
    const int tl = lane >> 3, lr = lane & 7;

    // lane-dependent ldmatrix offsets (halves), kk added inside loop
    // A tiles: (row8 block = tl&1, k8 block = tl>>1)
    const int aoff = ((tl & 1) * 8 + lr) * PAH + (tl >> 1) * 8 + wmI * 64 * PAH;
    // B tiles: (n8 block = tl>>1, k8 block = tl&1)
    const int boff = ((tl >> 1) * 8 + lr) * PAH + (tl & 1) * 8 + wnI * 32 * PAH;

    float acc[4][4][4];
    #pragma unroll
    for (int i = 0; i < 4; i++)
        #pragma unroll
        for (int j = 0; j < 4; j++)
            #pragma unroll
            for (int u = 0; u < 4; u++) acc[i][j][u] = 0.f;

    auto load_stage = [&](int s, int k0) {
        char* st = smem + s * STGB;
        #pragma unroll
        for (int i = 0; i < 2; i++) {
            int ch = tid + i * 256;
            int row = ch >> 2, c = ch & 3;
            cpasync16(st + row * 80 + c * 16,
                      A + (long)(m0 + row) * lda + k0 + c * 8);
        }
        char* stB = st + 128 * 80;
        #pragma unroll
        for (int i = 0; i < 2; i++) {
            int ch = tid + i * 256;
            int row = ch >> 2, c = ch & 3;
            cpasync16(stB + row * 80 + c * 16,
                      B + (long)(n0 + row) * ldb + k0 + c * 8);
        }
    };

    const int kt = K / 32;
    load_stage(0, 0);  cp_commit();
    load_stage(1, 32); cp_commit();

    for (int it = 0; it < kt; it++) {
        cp_wait<1>();
        __syncthreads();
        if (it + 2 < kt) load_stage((it + 2) % 3, (it + 2) * 32);
        cp_commit();

        const char* stg = smem + (it % 3) * STGB;
        unsigned int aB = (unsigned int)__cvta_generic_to_shared(stg) + aoff * 2;
        unsigned int bB = (unsigned int)__cvta_generic_to_shared(stg + 128 * 80) + boff * 2;

        #pragma unroll
        for (int kk = 0; kk < 32; kk += 16) {
            uint32_t af[4][4], bf[2][4];
            #pragma unroll
            for (int mf = 0; mf < 4; mf++)
                ldmx4(af[mf], aB + (mf * 16 * PAH + kk) * 2);
            #pragma unroll
            for (int np = 0; np < 2; np++)
                ldmx4(bf[np], bB + (np * 16 * PAH + kk) * 2);
            #pragma unroll
            for (int mf = 0; mf < 4; mf++) {
                mma_f16(acc[mf][0], af[mf], bf[0][0], bf[0][1]);
                mma_f16(acc[mf][1], af[mf], bf[0][2], bf[0][3]);
                mma_f16(acc[mf][2], af[mf], bf[1][0], bf[1][1]);
                mma_f16(acc[mf][3], af[mf], bf[1][2], bf[1][3]);
            }
        }
        __syncthreads();
    }

    #pragma unroll
    for (int nf = 0; nf < 4; nf++) {
        int col = n0 + wnI * 32 + nf * 8 + 2 * t4;
        float b0 = 0.f, b1 = 0.f;
        if (epi & 1) { b0 = bias[col]; b1 = bias[col + 1]; }
        #pragma unroll
        for (int mf = 0; mf < 4; mf++) {
            long r1 = m0 + wmI * 64 + mf * 16 + g;
            #pragma unroll
            for (int hh = 0; hh < 2; hh++) {
                long rr = r1 + hh * 8;
                float v0 = acc[mf][nf][hh * 2]     + b0;
                float v1 = acc[mf][nf][hh * 2 + 1] + b1;
                if (epi & 2) { v0 = gelu_f(v0); v1 = gelu_f(v1); }
                if (epi & 4) { v0 += Res[rr * ldc + col]; v1 += Res[rr * ldc + col + 1]; }
                if constexpr (sizeof(CT) == 2) {
                    __half2 hv = __floats2half2_rn(v0, v1);
                    *(__half2*)((__half*)C + rr * ldc + col) = hv;
                } else {
                    *(float2*)((float*)C + rr * ldc + col) = make_float2(v0, v1);
                }
            }
        }
    }
}

// ---------------- flash attention (ldmatrix everywhere) ----------------
#define FKB 18432            // 128 x 72 halves (144B pitch)
#define FSMEM (4 * FKB)      // 73728

__global__ void __launch_bounds__(256) flash_kernel(
    const __half* __restrict__ QKV, __half* __restrict__ O)
{
    extern __shared__ char sm[];
    const int tid = threadIdx.x;
    const int wid = tid >> 5, lane = tid & 31;
    const int g = lane >> 2, t4 = lane & 3;
    const int tl = lane >> 3, lr = lane & 7;
    const int wrow = wid * 16;

    const int bh = blockIdx.y;
    const long tok0 = (long)(bh >> 4) * SEQ;
    const int hd0 = (bh & 15) * HEADD;
    const int q0 = blockIdx.x * 128;

    // Q a-frags (scaled by 1/8, exact in fp16)
    const __half* qp = QKV + (tok0 + q0) * D3 + hd0;
    uint32_t qa[4][4];
    const __half2 qs = __half2half2(__float2half(0.125f));
    #pragma unroll
    for (int ks = 0; ks < 4; ks++) {
        int col = ks * 16 + 2 * t4;
        __half2 a0 = __hmul2(*(const __half2*)(qp + (long)(wrow + g) * D3 + col), qs);
        __half2 a1 = __hmul2(*(const __half2*)(qp + (long)(wrow + g + 8) * D3 + col), qs);
        __half2 a2 = __hmul2(*(const __half2*)(qp + (long)(wrow + g) * D3 + col + 8), qs);
        __half2 a3 = __hmul2(*(const __half2*)(qp + (long)(wrow + g + 8) * D3 + col + 8), qs);
        qa[ks][0] = *(uint32_t*)&a0; qa[ks][1] = *(uint32_t*)&a1;
        qa[ks][2] = *(uint32_t*)&a2; qa[ks][3] = *(uint32_t*)&a3;
    }

    float m0 = -1e30f, m1 = -1e30f, l0 = 0.f, l1 = 0.f;
    float oacc[8][4];
    #pragma unroll
    for (int i = 0; i < 8; i++)
        #pragma unroll
        for (int u = 0; u < 4; u++) oacc[i][u] = 0.f;

    auto loadKV = [&](int j) {
        int bb = j & 1;
        char* sK = sm + bb * FKB;
        char* sV = sm + (2 + bb) * FKB;
        const __half* kp = QKV + (tok0 + j * 128) * D3 + DMODEL + hd0;
        const __half* vp = QKV + (tok0 + j * 128) * D3 + 2 * DMODEL + hd0;
        #pragma unroll
        for (int i = 0; i < 4; i++) {
            int ch = tid + i * 256;
            int row = ch >> 3, c = ch & 7;
            cpasync16(sK + row * 144 + c * 16, kp + (long)row * D3 + c * 8);
        }
        #pragma unroll
        for (int i = 0; i < 4; i++) {
            int ch = tid + i * 256;
            int row = ch >> 3, c = ch & 7;
            cpasync16(sV + row * 144 + c * 16, vp + (long)row * D3 + c * 8);
        }
    };

    // ldmatrix lane offsets
    // K (B-frag, non-trans): n-tile = tl>>1, k-tile = tl&1
    const int koff = (((tl >> 1) * 8 + lr) * 72 + (tl & 1) * 8) * 2;
    // V (trans): k row = (tl&1)*8 + lr, n col = (tl>>1)*8
    const int voff = (((tl & 1) * 8 + lr) * 72 + (tl >> 1) * 8) * 2;

    const int NC = SEQ / 128;   // 16
    loadKV(0); cp_commit();

    for (int j = 0; j < NC; j++) {
        cp_wait<0>();
        __syncthreads();
        if (j + 1 < NC) { loadKV(j + 1); cp_commit(); }

        unsigned int sKb = (unsigned int)__cvta_generic_to_shared(sm + (j & 1) * FKB);
        unsigned int sVb = (unsigned int)__cvta_generic_to_shared(sm + (2 + (j & 1)) * FKB);

        // ---- S = (Q/8) @ K^T ----
        float sacc[16][4];
        #pragma unroll
        for (int i = 0; i < 16; i++)
            #pragma unroll
            for (int u = 0; u < 4; u++) sacc[i][u] = 0.f;
        #pragma unroll
        for (int ks = 0; ks < 4; ks++) {
            #pragma unroll
            for (int np = 0; np < 8; np++) {
                uint32_t bf[4];
                ldmx4(bf, sKb + koff + (np * 16 * 72 + ks * 16) * 2);
                mma_f16(sacc[2 * np],     qa[ks], bf[0], bf[1]);
                mma_f16(sacc[2 * np + 1], qa[ks], bf[2], bf[3]);
            }
        }

        // ---- online softmax (in registers) ----
        float mx0 = -1e30f, mx1 = -1e30f;
        #pragma unroll
        for (int nf = 0; nf < 16; nf++) {
            mx0 = fmaxf(mx0, fmaxf(sacc[nf][0], sacc[nf][1]));
            mx1 = fmaxf(mx1, fmaxf(sacc[nf][2], sacc[nf][3]));
        }
        mx0 = fmaxf(mx0, __shfl_xor_sync(0xffffffffu, mx0, 1));
        mx0 = fmaxf(mx0, __shfl_xor_sync(0xffffffffu, mx0, 2));
        mx1 = fmaxf(mx1, __shfl_xor_sync(0xffffffffu, mx1, 1));
        mx1 = fmaxf(mx1, __shfl_xor_sync(0xffffffffu, mx1, 2));
        float nm0 = fmaxf(m0, mx0), nm1 = fmaxf(m1, mx1);
        float cr0 = __expf(m0 - nm0), cr1 = __expf(m1 - nm1);
        m0 = nm0; m1 = nm1;

        float rs0 = 0.f, rs1 = 0.f;
        #pragma unroll
        for (int nf = 0; nf < 16; nf++) {
            sacc[nf][0] = __expf(sacc[nf][0] - m0);
            sacc[nf][1] = __expf(sacc[nf][1] - m0);
            sacc[nf][2] = __expf(sacc[nf][2] - m1);
            sacc[nf][3] = __expf(sacc[nf][3] - m1);
            rs0 += sacc[nf][0] + sacc[nf][1];
            rs1 += sacc[nf][2] + sacc[nf][3];
        }
        rs0 += __shfl_xor_sync(0xffffffffu, rs0, 1);
        rs0 += __shfl_xor_sync(0xffffffffu, rs0, 2);
        rs1 += __shfl_xor_sync(0xffffffffu, rs1, 1);
        rs1 += __shfl_xor_sync(0xffffffffu, rs1, 2);
        l0 = l0 * cr0 + rs0;
        l1 = l1 * cr1 + rs1;
        #pragma unroll
        for (int nf = 0; nf < 8; nf++) {
            oacc[nf][0] *= cr0; oacc[nf][1] *= cr0;
            oacc[nf][2] *= cr1; oacc[nf][3] *= cr1;
        }

        // ---- O += P @ V, register P, ldmatrix.trans V ----
        #pragma unroll
        for (int kc = 0; kc < 8; kc++) {
            uint32_t a[4];
            __half2 p0 = __floats2half2_rn(sacc[2 * kc][0],     sacc[2 * kc][1]);
            __half2 p1 = __floats2half2_rn(sacc[2 * kc][2],     sacc[2 * kc][3]);
            __half2 p2 = __floats2half2_rn(sacc[2 * kc + 1][0], sacc[2 * kc + 1][1]);
            __half2 p3 = __floats2half2_rn(sacc[2 * kc + 1][2], sacc[2 * kc + 1][3]);
            a[0] = *(uint32_t*)&p0; a[1] = *(uint32_t*)&p1;
            a[2] = *(uint32_t*)&p2; a[3] = *(uint32_t*)&p3;
            #pragma unroll
            for (int np = 0; np < 4; np++) {
                uint32_t vr[4];
                ldmx4t(vr, sVb + voff + (kc * 16 * 72 + np * 16) * 2);
                mma_f16(oacc[2 * np],     a, vr[0], vr[1]);
                mma_f16(oacc[2 * np + 1], a, vr[2], vr[3]);
            }
        }
    }

    // ---- write O ----
    float i0 = 1.0f / l0, i1 = 1.0f / l1;
    __half* op = O + (tok0 + q0) * DMODEL + hd0;
    #pragma unroll
    for (int nf = 0; nf < 8; nf++) {
        int col = nf * 8 + 2 * t4;
        __half2 h0 = __floats2half2_rn(oacc[nf][0] * i0, oacc[nf][1] * i0);
        __half2 h1 = __floats2half2_rn(oacc[nf][2] * i1, oacc[nf][3] * i1);
        *(__half2*)(op + (long)(wrow + g) * DMODEL + col) = h0;
        *(__half2*)(op + (long)(wrow + g + 8) * DMODEL + col) = h1;
    }
}

// ---------------- launch ----------------
extern "C" void kernel_launch(void* const* d_in, const int* in_sizes, int n_in,
                              void* d_out, int out_size)
{
    const float* x   = (const float*)d_in[0];
    const float* Wq  = (const float*)d_in[1];
    const float* bq  = (const float*)d_in[2];
    const float* Wk  = (const float*)d_in[3];
    const float* bk  = (const float*)d_in[4];
    const float* Wv  = (const float*)d_in[5];
    const float* bv  = (const float*)d_in[6];
    const float* Wp  = (const float*)d_in[7];
    const float* bp  = (const float*)d_in[8];
    const float* W1  = (const float*)d_in[9];
    const float* b1  = (const float*)d_in[10];
    const float* W2  = (const float*)d_in[11];
    const float* b2  = (const float*)d_in[12];
    const float* g1  = (const float*)d_in[13];
    const float* be1 = (const float*)d_in[14];
    const float* g2  = (const float*)d_in[15];
    const float* be2 = (const float*)d_in[16];
    float* out = (float*)d_out;

    __half *h, *qkv, *att, *h2, *ff, *wqkv, *wp, *w1, *w2;
    float *x1, *bqkv;
    cudaGetSymbolAddress((void**)&h,    g_h);
    cudaGetSymbolAddress((void**)&qkv,  g_qkv);
    cudaGetSymbolAddress((void**)&att,  g_att);
    cudaGetSymbolAddress((void**)&x1,   g_x1);
    cudaGetSymbolAddress((void**)&h2,   g_h2);
    cudaGetSymbolAddress((void**)&ff,   g_ff);
    cudaGetSymbolAddress((void**)&wqkv, g_wqkv);
    cudaGetSymbolAddress((void**)&bqkv, g_bqkv);
    cudaGetSymbolAddress((void**)&wp,   g_wp);
    cudaGetSymbolAddress((void**)&w1,   g_w1);
    cudaGetSymbolAddress((void**)&w2,   g_w2);

    const int smemG = 3 * 2 * 128 * PAH * 2;   // 61440
    static bool attr_done = false;
    if (!attr_done) {
        cudaFuncSetAttribute(hgemm<__half>,
            cudaFuncAttributeMaxDynamicSharedMemorySize, smemG);
        cudaFuncSetAttribute(hgemm<float>,
            cudaFuncAttributeMaxDynamicSharedMemorySize, smemG);
        cudaFuncSetAttribute(flash_kernel,
            cudaFuncAttributeMaxDynamicSharedMemorySize, FSMEM);
        attr_done = true;
    }

    dim3 tb(32, 8);
    wtrans<<<dim3(DMODEL / 32, DMODEL / 32), tb>>>(Wq, wqkv, DMODEL, DMODEL);
    wtrans<<<dim3(DMODEL / 32, DMODEL / 32), tb>>>(Wk, wqkv + (size_t)DMODEL * DMODEL, DMODEL, DMODEL);
    wtrans<<<dim3(DMODEL / 32, DMODEL / 32), tb>>>(Wv, wqkv + (size_t)2 * DMODEL * DMODEL, DMODEL, DMODEL);
    bcat<<<12, 256>>>(bq, bk, bv, bqkv);
    wtrans<<<dim3(DMODEL / 32, DMODEL / 32), tb>>>(Wp, wp, DMODEL, DMODEL);
    wtrans<<<dim3(DFF / 32, DMODEL / 32), tb>>>(W1, w1, DMODEL, DFF);
    wtrans<<<dim3(DMODEL / 32, DFF / 32), tb>>>(W2, w2, DFF, DMODEL);

    ln_kernel<<<NTOK, 256>>>(x, g1, be1, h);

    dim3 gQKV(D3 / 128, NTOK / 128);
    hgemm<__half><<<gQKV, 256, smemG>>>(h, wqkv, bqkv, nullptr, qkv,
                                        DMODEL, DMODEL, DMODEL, D3, 1);

    flash_kernel<<<dim3(SEQ / 128, NBATCH * NHEADS), 256, FSMEM>>>(qkv, att);

    dim3 gP(DMODEL / 128, NTOK / 128);
    hgemm<float><<<gP, 256, smemG>>>(att, wp, bp, x, x1, DMODEL, DMODEL, DMODEL, DMODEL, 1 | 4);

    ln_kernel<<<NTOK, 256>>>(x1, g2, be2, h2);

    dim3 gF1(DFF / 128, NTOK / 128);
    hgemm<__half><<<gF1, 256, smemG>>>(h2, w1, b1, nullptr, ff, DMODEL, DMODEL, DMODEL, DFF, 1 | 2);

    dim3 gF2(DMODEL / 128, NTOK / 128);
    hgemm<float><<<gF2, 256, smemG>>>(ff, w2, b2, x1, out, DFF, DFF, DFF, DMODEL, 1 | 4);
}